// round 2
// baseline (speedup 1.0000x reference)
#include <cuda_runtime.h>

#define SQ 2048
#define NB 4
#define NH 16
#define HD 64
#define DM 1024
#define PAD 68

// Scratch for Q/K/V in [B, H, S, d] layout (allocation-guard-safe device globals)
__device__ float g_q[NB * NH * SQ * HD];
__device__ float g_k[NB * NH * SQ * HD];
__device__ float g_v[NB * NH * SQ * HD];

typedef unsigned long long u64;

// ---- packed 2xfp32 helpers (B300: FFMA2 is 2x FLOP/issue vs 3-reg FFMA) ----
__device__ __forceinline__ u64 pack2(float x, float y) {
    u64 r; asm("mov.b64 %0, {%1, %2};" : "=l"(r) : "f"(x), "f"(y)); return r;
}
__device__ __forceinline__ u64 dup2(float x) {
    u64 r; asm("mov.b64 %0, {%1, %1};" : "=l"(r) : "f"(x)); return r;
}
__device__ __forceinline__ void unpack2(u64 v, float& x, float& y) {
    asm("mov.b64 {%0, %1}, %2;" : "=f"(x), "=f"(y) : "l"(v));
}
__device__ __forceinline__ void ffma2(u64& d, u64 a, u64 b) {
    asm("fma.rn.f32x2 %0, %1, %2, %0;" : "+l"(d) : "l"(a), "l"(b));
}
__device__ __forceinline__ void mul2(u64& d, u64 a) {
    asm("mul.rn.f32x2 %0, %0, %1;" : "+l"(d) : "l"(a));
}

// ============================================================================
// Fused QKV projection: out = X @ W^T + b, written into [B,H,S,d] layout.
// M=8192, N=1024, K=1024. 128x128 tile, BK=16, 256 threads, 8x8 per thread.
// gridDim.z selects Q / K / V.
// ============================================================================
__global__ __launch_bounds__(256, 2) void qkv_gemm(
    const float* __restrict__ X,
    const float* __restrict__ Wq, const float* __restrict__ bq,
    const float* __restrict__ Wk, const float* __restrict__ bk,
    const float* __restrict__ Wv, const float* __restrict__ bv)
{
    __shared__ float As[16][132];  // transposed: As[k][m]
    __shared__ float Bs[16][132];  // transposed: Bs[k][n]

    const int z = blockIdx.z;
    const float* W    = (z == 0) ? Wq : (z == 1) ? Wk : Wv;
    const float* bias = (z == 0) ? bq : (z == 1) ? bk : bv;
    float* dst        = (z == 0) ? g_q : (z == 1) ? g_k : g_v;

    const int tid = threadIdx.x;
    const int tx = tid & 15, ty = tid >> 4;
    const int m0 = blockIdx.y * 128, n0 = blockIdx.x * 128;

    const int lr = tid >> 1;          // tile row 0..127
    const int lc = (tid & 1) * 8;     // k offset 0 or 8
    const float* Ap = X + (size_t)(m0 + lr) * DM + lc;
    const float* Wp = W + (size_t)(n0 + lr) * DM + lc;

    u64 acc[8][4];
    #pragma unroll
    for (int i = 0; i < 8; i++)
        #pragma unroll
        for (int j = 0; j < 4; j++) acc[i][j] = 0ULL;

    for (int k0 = 0; k0 < DM; k0 += 16) {
        float4 a0 = *(const float4*)(Ap + k0);
        float4 a1 = *(const float4*)(Ap + k0 + 4);
        float4 b0 = *(const float4*)(Wp + k0);
        float4 b1 = *(const float4*)(Wp + k0 + 4);
        __syncthreads();
        As[lc + 0][lr] = a0.x; As[lc + 1][lr] = a0.y;
        As[lc + 2][lr] = a0.z; As[lc + 3][lr] = a0.w;
        As[lc + 4][lr] = a1.x; As[lc + 5][lr] = a1.y;
        As[lc + 6][lr] = a1.z; As[lc + 7][lr] = a1.w;
        Bs[lc + 0][lr] = b0.x; Bs[lc + 1][lr] = b0.y;
        Bs[lc + 2][lr] = b0.z; Bs[lc + 3][lr] = b0.w;
        Bs[lc + 4][lr] = b1.x; Bs[lc + 5][lr] = b1.y;
        Bs[lc + 6][lr] = b1.z; Bs[lc + 7][lr] = b1.w;
        __syncthreads();

        #pragma unroll
        for (int kk = 0; kk < 16; kk++) {
            float4 af0 = *(const float4*)&As[kk][ty * 8];
            float4 af1 = *(const float4*)&As[kk][ty * 8 + 4];
            float4 bf0 = *(const float4*)&Bs[kk][tx * 8];
            float4 bf1 = *(const float4*)&Bs[kk][tx * 8 + 4];
            u64 bb[4] = { pack2(bf0.x, bf0.y), pack2(bf0.z, bf0.w),
                          pack2(bf1.x, bf1.y), pack2(bf1.z, bf1.w) };
            float av[8] = { af0.x, af0.y, af0.z, af0.w,
                            af1.x, af1.y, af1.z, af1.w };
            #pragma unroll
            for (int i = 0; i < 8; i++) {
                u64 ad = dup2(av[i]);
                ffma2(acc[i][0], ad, bb[0]);
                ffma2(acc[i][1], ad, bb[1]);
                ffma2(acc[i][2], ad, bb[2]);
                ffma2(acc[i][3], ad, bb[3]);
            }
        }
    }

    const int n = n0 + tx * 8;       // 8 cols stay within one 64-wide head slice
    const int h = n >> 6, dd = n & 63;
    float bv8[8];
    #pragma unroll
    for (int j = 0; j < 8; j++) bv8[j] = bias[n + j];

    #pragma unroll
    for (int i = 0; i < 8; i++) {
        const int m = m0 + ty * 8 + i;
        const int b = m >> 11, s = m & (SQ - 1);
        float v[8];
        unpack2(acc[i][0], v[0], v[1]); unpack2(acc[i][1], v[2], v[3]);
        unpack2(acc[i][2], v[4], v[5]); unpack2(acc[i][3], v[6], v[7]);
        #pragma unroll
        for (int j = 0; j < 8; j++) v[j] += bv8[j];
        float* o = dst + ((size_t)(b * NH + h) * SQ + s) * HD + dd;
        *(float4*)(o)     = make_float4(v[0], v[1], v[2], v[3]);
        *(float4*)(o + 4) = make_float4(v[4], v[5], v[6], v[7]);
    }
}

// ============================================================================
// Flash attention, fp32, online softmax. One block per (q_tile of 64, b*h).
// 256 threads; each owns a 4x4 sub-tile (ty->4 rows, tx->4 cols).
// Row reductions via shfl_xor over tx (lane bits 0..3).
// ============================================================================
__global__ __launch_bounds__(256, 2) void flash_attn(
    const float* __restrict__ mask, float* __restrict__ out)
{
    extern __shared__ float smf[];
    float* Qt = smf;                 // [64][PAD] : Qt[k][r], pre-scaled by 1/8
    float* Kt = Qt + 64 * PAD;       // [64][PAD] : Kt[k][c]
    float* Vs = Kt + 64 * PAD;       // [64][PAD] : Vs[c][dd]
    float* Pt = Vs + 64 * PAD;       // [64][PAD] : Pt[c][r]

    const int tid = threadIdx.x;
    const int tx = tid & 15, ty = tid >> 4;
    const int bh = blockIdx.y;
    const int b = bh >> 4, h = bh & 15;
    const int q0 = blockIdx.x * 64;

    const float* Qg = g_q + ((size_t)bh * SQ + q0) * HD;
    const float* Kg = g_k + (size_t)bh * SQ * HD;
    const float* Vg = g_v + (size_t)bh * SQ * HD;
    const float* mrow = mask + (size_t)b * SQ;

    // Load Q tile transposed, folding in softmax scale 1/sqrt(64)
    {
        const int r = tid >> 2;
        const int kq = (tid & 3) * 16;
        #pragma unroll
        for (int w = 0; w < 4; w++) {
            float4 v = *(const float4*)(Qg + (size_t)r * HD + kq + w * 4);
            Qt[(kq + w * 4 + 0) * PAD + r] = v.x * 0.125f;
            Qt[(kq + w * 4 + 1) * PAD + r] = v.y * 0.125f;
            Qt[(kq + w * 4 + 2) * PAD + r] = v.z * 0.125f;
            Qt[(kq + w * 4 + 3) * PAD + r] = v.w * 0.125f;
        }
    }

    const int r0 = ty * 4, c0 = tx * 4;
    float m_i[4] = { -1e30f, -1e30f, -1e30f, -1e30f };
    float l_i[4] = { 0.f, 0.f, 0.f, 0.f };
    u64 o2[4][2];
    #pragma unroll
    for (int i = 0; i < 4; i++) { o2[i][0] = 0ULL; o2[i][1] = 0ULL; }

    for (int j0 = 0; j0 < SQ; j0 += 64) {
        // ---- load K (transposed) + V (direct) tiles ----
        const int r = tid >> 2;
        const int cq = (tid & 3) * 16;
        float4 kv[4], vv[4];
        #pragma unroll
        for (int w = 0; w < 4; w++) {
            kv[w] = *(const float4*)(Kg + (size_t)(j0 + r) * HD + cq + w * 4);
            vv[w] = *(const float4*)(Vg + (size_t)(j0 + r) * HD + cq + w * 4);
        }
        __syncthreads();   // previous iteration's PV reads are done
        #pragma unroll
        for (int w = 0; w < 4; w++) {
            Kt[(cq + w * 4 + 0) * PAD + r] = kv[w].x;
            Kt[(cq + w * 4 + 1) * PAD + r] = kv[w].y;
            Kt[(cq + w * 4 + 2) * PAD + r] = kv[w].z;
            Kt[(cq + w * 4 + 3) * PAD + r] = kv[w].w;
            *(float4*)&Vs[r * PAD + cq + w * 4] = vv[w];
        }
        __syncthreads();

        // ---- S = (Q*scale) @ K^T on the 4x4 sub-tile ----
        u64 s2[4][2];
        #pragma unroll
        for (int i = 0; i < 4; i++) { s2[i][0] = 0ULL; s2[i][1] = 0ULL; }
        #pragma unroll 8
        for (int k = 0; k < 64; k++) {
            float4 qv = *(const float4*)&Qt[k * PAD + r0];
            float4 kk = *(const float4*)&Kt[k * PAD + c0];
            u64 kb0 = pack2(kk.x, kk.y), kb1 = pack2(kk.z, kk.w);
            float qa[4] = { qv.x, qv.y, qv.z, qv.w };
            #pragma unroll
            for (int i = 0; i < 4; i++) {
                u64 qd = dup2(qa[i]);
                ffma2(s2[i][0], qd, kb0);
                ffma2(s2[i][1], qd, kb1);
            }
        }

        float sc[4][4];
        float mk[4];
        #pragma unroll
        for (int j = 0; j < 4; j++) mk[j] = mrow[j0 + c0 + j];
        #pragma unroll
        for (int i = 0; i < 4; i++) {
            unpack2(s2[i][0], sc[i][0], sc[i][1]);
            unpack2(s2[i][1], sc[i][2], sc[i][3]);
            #pragma unroll
            for (int j = 0; j < 4; j++) sc[i][j] += mk[j];
        }

        // ---- online softmax ----
        float rm[4], rs[4], mn[4], alpha[4];
        #pragma unroll
        for (int i = 0; i < 4; i++) {
            rm[i] = fmaxf(fmaxf(sc[i][0], sc[i][1]), fmaxf(sc[i][2], sc[i][3]));
        }
        #pragma unroll
        for (int w = 1; w < 16; w <<= 1)
            #pragma unroll
            for (int i = 0; i < 4; i++)
                rm[i] = fmaxf(rm[i], __shfl_xor_sync(0xffffffffu, rm[i], w));
        #pragma unroll
        for (int i = 0; i < 4; i++) {
            mn[i] = fmaxf(m_i[i], rm[i]);
            alpha[i] = __expf(m_i[i] - mn[i]);
            m_i[i] = mn[i];
            float p0 = __expf(sc[i][0] - mn[i]);
            float p1 = __expf(sc[i][1] - mn[i]);
            float p2 = __expf(sc[i][2] - mn[i]);
            float p3 = __expf(sc[i][3] - mn[i]);
            sc[i][0] = p0; sc[i][1] = p1; sc[i][2] = p2; sc[i][3] = p3;
            rs[i] = p0 + p1 + p2 + p3;
        }
        #pragma unroll
        for (int w = 1; w < 16; w <<= 1)
            #pragma unroll
            for (int i = 0; i < 4; i++)
                rs[i] += __shfl_xor_sync(0xffffffffu, rs[i], w);
        #pragma unroll
        for (int i = 0; i < 4; i++) {
            l_i[i] = l_i[i] * alpha[i] + rs[i];
            u64 ad = dup2(alpha[i]);
            mul2(o2[i][0], ad);
            mul2(o2[i][1], ad);
        }

        // ---- write P transposed for the PV pass ----
        #pragma unroll
        for (int j = 0; j < 4; j++) {
            *(float4*)&Pt[(c0 + j) * PAD + r0] =
                make_float4(sc[0][j], sc[1][j], sc[2][j], sc[3][j]);
        }
        __syncthreads();

        // ---- O += P @ V on the 4x4 sub-tile (rows r0.., cols dd0 = tx*4) ----
        #pragma unroll 8
        for (int c = 0; c < 64; c++) {
            float4 pv = *(const float4*)&Pt[c * PAD + r0];
            float4 vx = *(const float4*)&Vs[c * PAD + c0];
            u64 vb0 = pack2(vx.x, vx.y), vb1 = pack2(vx.z, vx.w);
            float pa[4] = { pv.x, pv.y, pv.z, pv.w };
            #pragma unroll
            for (int i = 0; i < 4; i++) {
                u64 pd = dup2(pa[i]);
                ffma2(o2[i][0], pd, vb0);
                ffma2(o2[i][1], pd, vb1);
            }
        }
    }

    // ---- epilogue: normalize, write to [B, S, H*d] ----
    #pragma unroll
    for (int i = 0; i < 4; i++) {
        float inv = 1.0f / l_i[i];
        float v0, v1, v2, v3;
        unpack2(o2[i][0], v0, v1);
        unpack2(o2[i][1], v2, v3);
        const int s = q0 + r0 + i;
        float* op = out + ((size_t)b * SQ + s) * DM + h * HD + c0;
        *(float4*)op = make_float4(v0 * inv, v1 * inv, v2 * inv, v3 * inv);
    }
}

extern "C" void kernel_launch(void* const* d_in, const int* in_sizes, int n_in,
                              void* d_out, int out_size)
{
    const float* X   = (const float*)d_in[0];
    const float* Mk  = (const float*)d_in[1];
    const float* Wq  = (const float*)d_in[2];
    const float* bq  = (const float*)d_in[3];
    const float* Wk  = (const float*)d_in[4];
    const float* bk  = (const float*)d_in[5];
    const float* Wv  = (const float*)d_in[6];
    const float* bv  = (const float*)d_in[7];
    float* out = (float*)d_out;

    const int smem_attn = 4 * 64 * PAD * (int)sizeof(float);  // 69632 B
    cudaFuncSetAttribute(flash_attn, cudaFuncAttributeMaxDynamicSharedMemorySize,
                         smem_attn);

    qkv_gemm<<<dim3(8, 64, 3), 256>>>(X, Wq, bq, Wk, bk, Wv, bv);
    flash_attn<<<dim3(SQ / 64, NB * NH), 256, smem_attn>>>(Mk, out);
}

// round 4
// speedup vs baseline: 1.2573x; 1.2573x over previous
#include <cuda_runtime.h>
#include <cuda_bf16.h>
#include <cstdint>

#define SQ 2048
#define NB 4
#define NH 16
#define HD 64
#define DM 1024
#define PAD 68

// Scratch for Q/K/V in [B, H, S, d] layout (allocation-guard-safe device globals)
__device__ float g_q[NB * NH * SQ * HD];
__device__ float g_k[NB * NH * SQ * HD];
__device__ float g_v[NB * NH * SQ * HD];

typedef unsigned long long u64;

// ---- packed 2xfp32 helpers (flash kernel) ----
__device__ __forceinline__ u64 pack2(float x, float y) {
    u64 r; asm("mov.b64 %0, {%1, %2};" : "=l"(r) : "f"(x), "f"(y)); return r;
}
__device__ __forceinline__ u64 dup2(float x) {
    u64 r; asm("mov.b64 %0, {%1, %1};" : "=l"(r) : "f"(x)); return r;
}
__device__ __forceinline__ void unpack2(u64 v, float& x, float& y) {
    asm("mov.b64 {%0, %1}, %2;" : "=f"(x), "=f"(y) : "l"(v));
}
__device__ __forceinline__ void ffma2(u64& d, u64 a, u64 b) {
    asm("fma.rn.f32x2 %0, %1, %2, %0;" : "+l"(d) : "l"(a), "l"(b));
}
__device__ __forceinline__ void mul2(u64& d, u64 a) {
    asm("mul.rn.f32x2 %0, %0, %1;" : "+l"(d) : "l"(a));
}

// ---- mma.sync m16n8k16 bf16 (compute_103-legal; lowers to HMMA on sm_103a) ----
__device__ __forceinline__ void mma16816(float* d, const uint32_t* a,
                                         uint32_t b0, uint32_t b1) {
    asm volatile(
        "mma.sync.aligned.m16n8k16.row.col.f32.bf16.bf16.f32 "
        "{%0,%1,%2,%3}, {%4,%5,%6,%7}, {%8,%9}, {%0,%1,%2,%3};"
        : "+f"(d[0]), "+f"(d[1]), "+f"(d[2]), "+f"(d[3])
        : "r"(a[0]), "r"(a[1]), "r"(a[2]), "r"(a[3]), "r"(b0), "r"(b1));
}

// ============================================================================
// QKV projection via mma.sync split-bf16: out = X @ W^T + b, into [B,H,S,d].
// CTA tile 128(M) x 128(N), K chunk 32 bf16. 8 warps = 4(M) x 2(N), each warp
// a 32x64 sub-tile. Split precision: D = Ah*Bh + Al*Bh + Ah*Bl (err ~2^-17).
// ============================================================================
#define KC 32
#define APITCH 40   // bf16 pitch: conflict-free fragment LDS

__global__ __launch_bounds__(256) void qkv_gemm_mma(
    const float* __restrict__ X,
    const float* __restrict__ Wq, const float* __restrict__ bq,
    const float* __restrict__ Wk, const float* __restrict__ bk,
    const float* __restrict__ Wv, const float* __restrict__ bv)
{
    __shared__ __align__(16) __nv_bfloat16 Ah[128][APITCH];
    __shared__ __align__(16) __nv_bfloat16 Al[128][APITCH];
    __shared__ __align__(16) __nv_bfloat16 Bh[128][APITCH];
    __shared__ __align__(16) __nv_bfloat16 Bl[128][APITCH];

    const int z = blockIdx.z;
    const float* W    = (z == 0) ? Wq : (z == 1) ? Wk : Wv;
    const float* bias = (z == 0) ? bq : (z == 1) ? bk : bv;
    float* dst        = (z == 0) ? g_q : (z == 1) ? g_k : g_v;

    const int tid = threadIdx.x;
    const int wid = tid >> 5, lane = tid & 31;
    const int wm = wid & 3, wn = wid >> 2;
    const int m0 = blockIdx.y * 128, n0 = blockIdx.x * 128;

    const int lrow = tid >> 1;            // 0..127
    const int lcol = (tid & 1) * 16;      // 0 or 16
    const float* Ap = X + (size_t)(m0 + lrow) * DM + lcol;
    const float* Bp = W + (size_t)(n0 + lrow) * DM + lcol;

    float acc[2][8][4];
    #pragma unroll
    for (int mt = 0; mt < 2; mt++)
        #pragma unroll
        for (int nt = 0; nt < 8; nt++)
            #pragma unroll
            for (int j = 0; j < 4; j++) acc[mt][nt][j] = 0.f;

    const int fr = lane >> 2;            // fragment row 0..7
    const int fc = (lane & 3) * 2;       // fragment col pair base

    for (int c = 0; c < DM / KC; c++) {
        const int k0 = c * KC;
        float va[16], vb[16];
        #pragma unroll
        for (int j = 0; j < 4; j++) {
            float4 t = *(const float4*)(Ap + k0 + j * 4);
            va[4*j] = t.x; va[4*j+1] = t.y; va[4*j+2] = t.z; va[4*j+3] = t.w;
            float4 u = *(const float4*)(Bp + k0 + j * 4);
            vb[4*j] = u.x; vb[4*j+1] = u.y; vb[4*j+2] = u.z; vb[4*j+3] = u.w;
        }
        __syncthreads();   // previous chunk's fragment reads done
        {
            uint32_t hp[8], lp[8], hq[8], lq[8];
            #pragma unroll
            for (int j = 0; j < 8; j++) {
                __nv_bfloat162 h2 = __floats2bfloat162_rn(va[2*j], va[2*j+1]);
                __nv_bfloat162 l2 = __floats2bfloat162_rn(
                    va[2*j]   - __bfloat162float(h2.x),
                    va[2*j+1] - __bfloat162float(h2.y));
                hp[j] = *(uint32_t*)&h2; lp[j] = *(uint32_t*)&l2;
                __nv_bfloat162 h3 = __floats2bfloat162_rn(vb[2*j], vb[2*j+1]);
                __nv_bfloat162 l3 = __floats2bfloat162_rn(
                    vb[2*j]   - __bfloat162float(h3.x),
                    vb[2*j+1] - __bfloat162float(h3.y));
                hq[j] = *(uint32_t*)&h3; lq[j] = *(uint32_t*)&l3;
            }
            *(uint4*)&Ah[lrow][lcol]     = make_uint4(hp[0], hp[1], hp[2], hp[3]);
            *(uint4*)&Ah[lrow][lcol + 8] = make_uint4(hp[4], hp[5], hp[6], hp[7]);
            *(uint4*)&Al[lrow][lcol]     = make_uint4(lp[0], lp[1], lp[2], lp[3]);
            *(uint4*)&Al[lrow][lcol + 8] = make_uint4(lp[4], lp[5], lp[6], lp[7]);
            *(uint4*)&Bh[lrow][lcol]     = make_uint4(hq[0], hq[1], hq[2], hq[3]);
            *(uint4*)&Bh[lrow][lcol + 8] = make_uint4(hq[4], hq[5], hq[6], hq[7]);
            *(uint4*)&Bl[lrow][lcol]     = make_uint4(lq[0], lq[1], lq[2], lq[3]);
            *(uint4*)&Bl[lrow][lcol + 8] = make_uint4(lq[4], lq[5], lq[6], lq[7]);
        }
        __syncthreads();

        #pragma unroll
        for (int kk = 0; kk < KC; kk += 16) {
            uint32_t ah[2][4], al[2][4];
            #pragma unroll
            for (int mt = 0; mt < 2; mt++) {
                const int rb = wm * 32 + mt * 16;
                const int cc = kk + fc;
                ah[mt][0] = *(const uint32_t*)&Ah[rb + fr][cc];
                ah[mt][1] = *(const uint32_t*)&Ah[rb + fr + 8][cc];
                ah[mt][2] = *(const uint32_t*)&Ah[rb + fr][cc + 8];
                ah[mt][3] = *(const uint32_t*)&Ah[rb + fr + 8][cc + 8];
                al[mt][0] = *(const uint32_t*)&Al[rb + fr][cc];
                al[mt][1] = *(const uint32_t*)&Al[rb + fr + 8][cc];
                al[mt][2] = *(const uint32_t*)&Al[rb + fr][cc + 8];
                al[mt][3] = *(const uint32_t*)&Al[rb + fr + 8][cc + 8];
            }
            #pragma unroll
            for (int nt = 0; nt < 8; nt++) {
                const int nb = wn * 64 + nt * 8 + fr;
                const int kc = kk + fc;
                uint32_t bh0 = *(const uint32_t*)&Bh[nb][kc];
                uint32_t bh1 = *(const uint32_t*)&Bh[nb][kc + 8];
                uint32_t bl0 = *(const uint32_t*)&Bl[nb][kc];
                uint32_t bl1 = *(const uint32_t*)&Bl[nb][kc + 8];
                #pragma unroll
                for (int mt = 0; mt < 2; mt++) {
                    mma16816(acc[mt][nt], ah[mt], bh0, bh1);
                    mma16816(acc[mt][nt], al[mt], bh0, bh1);
                    mma16816(acc[mt][nt], ah[mt], bl0, bl1);
                }
            }
        }
    }

    // ---- epilogue: +bias, write into [B, H, S, 64] scratch ----
    #pragma unroll
    for (int mt = 0; mt < 2; mt++) {
        const int row0 = m0 + wm * 32 + mt * 16 + fr;
        const int b0r = row0 >> 11, s0 = row0 & (SQ - 1);
        const int row1 = row0 + 8;
        const int b1r = row1 >> 11, s1 = row1 & (SQ - 1);
        #pragma unroll
        for (int nt = 0; nt < 8; nt++) {
            const int col = n0 + wn * 64 + nt * 8 + fc;
            const int h = col >> 6, dd = col & 63;
            const float bz0 = bias[col], bz1 = bias[col + 1];
            float* p0 = dst + ((size_t)(b0r * NH + h) * SQ + s0) * HD + dd;
            float* p1 = dst + ((size_t)(b1r * NH + h) * SQ + s1) * HD + dd;
            *(float2*)p0 = make_float2(acc[mt][nt][0] + bz0, acc[mt][nt][1] + bz1);
            *(float2*)p1 = make_float2(acc[mt][nt][2] + bz0, acc[mt][nt][3] + bz1);
        }
    }
}

// ============================================================================
// Flash attention, fp32, online softmax (unchanged — known-good baseline).
// ============================================================================
__global__ __launch_bounds__(256, 2) void flash_attn(
    const float* __restrict__ mask, float* __restrict__ out)
{
    extern __shared__ float smf[];
    float* Qt = smf;                 // [64][PAD] : Qt[k][r], pre-scaled by 1/8
    float* Kt = Qt + 64 * PAD;       // [64][PAD] : Kt[k][c]
    float* Vs = Kt + 64 * PAD;       // [64][PAD] : Vs[c][dd]
    float* Pt = Vs + 64 * PAD;       // [64][PAD] : Pt[c][r]

    const int tid = threadIdx.x;
    const int tx = tid & 15, ty = tid >> 4;
    const int bh = blockIdx.y;
    const int b = bh >> 4, h = bh & 15;
    const int q0 = blockIdx.x * 64;

    const float* Qg = g_q + ((size_t)bh * SQ + q0) * HD;
    const float* Kg = g_k + (size_t)bh * SQ * HD;
    const float* Vg = g_v + (size_t)bh * SQ * HD;
    const float* mrow = mask + (size_t)b * SQ;

    {
        const int r = tid >> 2;
        const int kq = (tid & 3) * 16;
        #pragma unroll
        for (int w = 0; w < 4; w++) {
            float4 v = *(const float4*)(Qg + (size_t)r * HD + kq + w * 4);
            Qt[(kq + w * 4 + 0) * PAD + r] = v.x * 0.125f;
            Qt[(kq + w * 4 + 1) * PAD + r] = v.y * 0.125f;
            Qt[(kq + w * 4 + 2) * PAD + r] = v.z * 0.125f;
            Qt[(kq + w * 4 + 3) * PAD + r] = v.w * 0.125f;
        }
    }

    const int r0 = ty * 4, c0 = tx * 4;
    float m_i[4] = { -1e30f, -1e30f, -1e30f, -1e30f };
    float l_i[4] = { 0.f, 0.f, 0.f, 0.f };
    u64 o2[4][2];
    #pragma unroll
    for (int i = 0; i < 4; i++) { o2[i][0] = 0ULL; o2[i][1] = 0ULL; }

    for (int j0 = 0; j0 < SQ; j0 += 64) {
        const int r = tid >> 2;
        const int cq = (tid & 3) * 16;
        float4 kv[4], vv[4];
        #pragma unroll
        for (int w = 0; w < 4; w++) {
            kv[w] = *(const float4*)(Kg + (size_t)(j0 + r) * HD + cq + w * 4);
            vv[w] = *(const float4*)(Vg + (size_t)(j0 + r) * HD + cq + w * 4);
        }
        __syncthreads();
        #pragma unroll
        for (int w = 0; w < 4; w++) {
            Kt[(cq + w * 4 + 0) * PAD + r] = kv[w].x;
            Kt[(cq + w * 4 + 1) * PAD + r] = kv[w].y;
            Kt[(cq + w * 4 + 2) * PAD + r] = kv[w].z;
            Kt[(cq + w * 4 + 3) * PAD + r] = kv[w].w;
            *(float4*)&Vs[r * PAD + cq + w * 4] = vv[w];
        }
        __syncthreads();

        u64 s2[4][2];
        #pragma unroll
        for (int i = 0; i < 4; i++) { s2[i][0] = 0ULL; s2[i][1] = 0ULL; }
        #pragma unroll 8
        for (int k = 0; k < 64; k++) {
            float4 qv = *(const float4*)&Qt[k * PAD + r0];
            float4 kk = *(const float4*)&Kt[k * PAD + c0];
            u64 kb0 = pack2(kk.x, kk.y), kb1 = pack2(kk.z, kk.w);
            float qa[4] = { qv.x, qv.y, qv.z, qv.w };
            #pragma unroll
            for (int i = 0; i < 4; i++) {
                u64 qd = dup2(qa[i]);
                ffma2(s2[i][0], qd, kb0);
                ffma2(s2[i][1], qd, kb1);
            }
        }

        float sc[4][4];
        float mk[4];
        #pragma unroll
        for (int j = 0; j < 4; j++) mk[j] = mrow[j0 + c0 + j];
        #pragma unroll
        for (int i = 0; i < 4; i++) {
            unpack2(s2[i][0], sc[i][0], sc[i][1]);
            unpack2(s2[i][1], sc[i][2], sc[i][3]);
            #pragma unroll
            for (int j = 0; j < 4; j++) sc[i][j] += mk[j];
        }

        float rm[4], rs[4], mn[4], alpha[4];
        #pragma unroll
        for (int i = 0; i < 4; i++) {
            rm[i] = fmaxf(fmaxf(sc[i][0], sc[i][1]), fmaxf(sc[i][2], sc[i][3]));
        }
        #pragma unroll
        for (int w = 1; w < 16; w <<= 1)
            #pragma unroll
            for (int i = 0; i < 4; i++)
                rm[i] = fmaxf(rm[i], __shfl_xor_sync(0xffffffffu, rm[i], w));
        #pragma unroll
        for (int i = 0; i < 4; i++) {
            mn[i] = fmaxf(m_i[i], rm[i]);
            alpha[i] = __expf(m_i[i] - mn[i]);
            m_i[i] = mn[i];
            float p0 = __expf(sc[i][0] - mn[i]);
            float p1 = __expf(sc[i][1] - mn[i]);
            float p2 = __expf(sc[i][2] - mn[i]);
            float p3 = __expf(sc[i][3] - mn[i]);
            sc[i][0] = p0; sc[i][1] = p1; sc[i][2] = p2; sc[i][3] = p3;
            rs[i] = p0 + p1 + p2 + p3;
        }
        #pragma unroll
        for (int w = 1; w < 16; w <<= 1)
            #pragma unroll
            for (int i = 0; i < 4; i++)
                rs[i] += __shfl_xor_sync(0xffffffffu, rs[i], w);
        #pragma unroll
        for (int i = 0; i < 4; i++) {
            l_i[i] = l_i[i] * alpha[i] + rs[i];
            u64 ad = dup2(alpha[i]);
            mul2(o2[i][0], ad);
            mul2(o2[i][1], ad);
        }

        #pragma unroll
        for (int j = 0; j < 4; j++) {
            *(float4*)&Pt[(c0 + j) * PAD + r0] =
                make_float4(sc[0][j], sc[1][j], sc[2][j], sc[3][j]);
        }
        __syncthreads();

        #pragma unroll 8
        for (int c = 0; c < 64; c++) {
            float4 pv = *(const float4*)&Pt[c * PAD + r0];
            float4 vx = *(const float4*)&Vs[c * PAD + c0];
            u64 vb0 = pack2(vx.x, vx.y), vb1 = pack2(vx.z, vx.w);
            float pa[4] = { pv.x, pv.y, pv.z, pv.w };
            #pragma unroll
            for (int i = 0; i < 4; i++) {
                u64 pd = dup2(pa[i]);
                ffma2(o2[i][0], pd, vb0);
                ffma2(o2[i][1], pd, vb1);
            }
        }
    }

    #pragma unroll
    for (int i = 0; i < 4; i++) {
        float inv = 1.0f / l_i[i];
        float v0, v1, v2, v3;
        unpack2(o2[i][0], v0, v1);
        unpack2(o2[i][1], v2, v3);
        const int s = q0 + r0 + i;
        float* op = out + ((size_t)b * SQ + s) * DM + h * HD + c0;
        *(float4*)op = make_float4(v0 * inv, v1 * inv, v2 * inv, v3 * inv);
    }
}

extern "C" void kernel_launch(void* const* d_in, const int* in_sizes, int n_in,
                              void* d_out, int out_size)
{
    const float* X   = (const float*)d_in[0];
    const float* Mk  = (const float*)d_in[1];
    const float* Wq  = (const float*)d_in[2];
    const float* bq  = (const float*)d_in[3];
    const float* Wk  = (const float*)d_in[4];
    const float* bk  = (const float*)d_in[5];
    const float* Wv  = (const float*)d_in[6];
    const float* bv  = (const float*)d_in[7];
    float* out = (float*)d_out;

    const int smem_attn = 4 * 64 * PAD * (int)sizeof(float);  // 69632 B
    cudaFuncSetAttribute(flash_attn, cudaFuncAttributeMaxDynamicSharedMemorySize,
                         smem_attn);

    qkv_gemm_mma<<<dim3(8, 64, 3), 256>>>(X, Wq, bq, Wk, bk, Wv, bv);
    flash_attn<<<dim3(SQ / 64, NB * NH), 256, smem_attn>>>(Mk, out);
}

// round 5
// speedup vs baseline: 2.0824x; 1.6562x over previous
#include <cuda_runtime.h>
#include <cuda_bf16.h>
#include <cuda_fp16.h>
#include <cstdint>

#define SQ 2048
#define NB 4
#define NH 16
#define HD 64
#define DM 1024

// Scratch for Q/K/V in [B, H, S, d] layout (allocation-guard-safe device globals)
__device__ float g_q[NB * NH * SQ * HD];
__device__ float g_k[NB * NH * SQ * HD];
__device__ float g_v[NB * NH * SQ * HD];

// ---- mma.sync m16n8k16 (compute_103-legal; lowers to HMMA on sm_103a) ----
__device__ __forceinline__ void mma16816(float* d, const uint32_t* a,
                                         uint32_t b0, uint32_t b1) {
    asm volatile(
        "mma.sync.aligned.m16n8k16.row.col.f32.bf16.bf16.f32 "
        "{%0,%1,%2,%3}, {%4,%5,%6,%7}, {%8,%9}, {%0,%1,%2,%3};"
        : "+f"(d[0]), "+f"(d[1]), "+f"(d[2]), "+f"(d[3])
        : "r"(a[0]), "r"(a[1]), "r"(a[2]), "r"(a[3]), "r"(b0), "r"(b1));
}
__device__ __forceinline__ void mma16816h(float* d, const uint32_t* a,
                                          uint32_t b0, uint32_t b1) {
    asm volatile(
        "mma.sync.aligned.m16n8k16.row.col.f32.f16.f16.f32 "
        "{%0,%1,%2,%3}, {%4,%5,%6,%7}, {%8,%9}, {%0,%1,%2,%3};"
        : "+f"(d[0]), "+f"(d[1]), "+f"(d[2]), "+f"(d[3])
        : "r"(a[0]), "r"(a[1]), "r"(a[2]), "r"(a[3]), "r"(b0), "r"(b1));
}
__device__ __forceinline__ uint32_t smem_u32(const void* p) {
    uint32_t a;
    asm("{ .reg .u64 t; cvta.to.shared.u64 t, %1; cvt.u32.u64 %0, t; }" : "=r"(a) : "l"(p));
    return a;
}
__device__ __forceinline__ void ldsm_x4(uint32_t& r0, uint32_t& r1, uint32_t& r2,
                                        uint32_t& r3, uint32_t addr) {
    asm volatile("ldmatrix.sync.aligned.m8n8.x4.shared.b16 {%0,%1,%2,%3}, [%4];"
                 : "=r"(r0), "=r"(r1), "=r"(r2), "=r"(r3) : "r"(addr));
}
__device__ __forceinline__ void ldsm_x4_t(uint32_t& r0, uint32_t& r1, uint32_t& r2,
                                          uint32_t& r3, uint32_t addr) {
    asm volatile("ldmatrix.sync.aligned.m8n8.x4.trans.shared.b16 {%0,%1,%2,%3}, [%4];"
                 : "=r"(r0), "=r"(r1), "=r"(r2), "=r"(r3) : "r"(addr));
}
__device__ __forceinline__ uint32_t h2bits(__half2 h) { return *(uint32_t*)&h; }

// ============================================================================
// QKV projection via mma.sync split-bf16 (unchanged from R3 — proven).
// ============================================================================
#define KC 32
#define APITCH 40

__global__ __launch_bounds__(256) void qkv_gemm_mma(
    const float* __restrict__ X,
    const float* __restrict__ Wq, const float* __restrict__ bq,
    const float* __restrict__ Wk, const float* __restrict__ bk,
    const float* __restrict__ Wv, const float* __restrict__ bv)
{
    __shared__ __align__(16) __nv_bfloat16 Ah[128][APITCH];
    __shared__ __align__(16) __nv_bfloat16 Al[128][APITCH];
    __shared__ __align__(16) __nv_bfloat16 Bh[128][APITCH];
    __shared__ __align__(16) __nv_bfloat16 Bl[128][APITCH];

    const int z = blockIdx.z;
    const float* W    = (z == 0) ? Wq : (z == 1) ? Wk : Wv;
    const float* bias = (z == 0) ? bq : (z == 1) ? bk : bv;
    float* dst        = (z == 0) ? g_q : (z == 1) ? g_k : g_v;

    const int tid = threadIdx.x;
    const int wid = tid >> 5, lane = tid & 31;
    const int wm = wid & 3, wn = wid >> 2;
    const int m0 = blockIdx.y * 128, n0 = blockIdx.x * 128;

    const int lrow = tid >> 1;
    const int lcol = (tid & 1) * 16;
    const float* Ap = X + (size_t)(m0 + lrow) * DM + lcol;
    const float* Bp = W + (size_t)(n0 + lrow) * DM + lcol;

    float acc[2][8][4];
    #pragma unroll
    for (int mt = 0; mt < 2; mt++)
        #pragma unroll
        for (int nt = 0; nt < 8; nt++)
            #pragma unroll
            for (int j = 0; j < 4; j++) acc[mt][nt][j] = 0.f;

    const int fr = lane >> 2;
    const int fc = (lane & 3) * 2;

    for (int c = 0; c < DM / KC; c++) {
        const int k0 = c * KC;
        float va[16], vb[16];
        #pragma unroll
        for (int j = 0; j < 4; j++) {
            float4 t = *(const float4*)(Ap + k0 + j * 4);
            va[4*j] = t.x; va[4*j+1] = t.y; va[4*j+2] = t.z; va[4*j+3] = t.w;
            float4 u = *(const float4*)(Bp + k0 + j * 4);
            vb[4*j] = u.x; vb[4*j+1] = u.y; vb[4*j+2] = u.z; vb[4*j+3] = u.w;
        }
        __syncthreads();
        {
            uint32_t hp[8], lp[8], hq[8], lq[8];
            #pragma unroll
            for (int j = 0; j < 8; j++) {
                __nv_bfloat162 h2 = __floats2bfloat162_rn(va[2*j], va[2*j+1]);
                __nv_bfloat162 l2 = __floats2bfloat162_rn(
                    va[2*j]   - __bfloat162float(h2.x),
                    va[2*j+1] - __bfloat162float(h2.y));
                hp[j] = *(uint32_t*)&h2; lp[j] = *(uint32_t*)&l2;
                __nv_bfloat162 h3 = __floats2bfloat162_rn(vb[2*j], vb[2*j+1]);
                __nv_bfloat162 l3 = __floats2bfloat162_rn(
                    vb[2*j]   - __bfloat162float(h3.x),
                    vb[2*j+1] - __bfloat162float(h3.y));
                hq[j] = *(uint32_t*)&h3; lq[j] = *(uint32_t*)&l3;
            }
            *(uint4*)&Ah[lrow][lcol]     = make_uint4(hp[0], hp[1], hp[2], hp[3]);
            *(uint4*)&Ah[lrow][lcol + 8] = make_uint4(hp[4], hp[5], hp[6], hp[7]);
            *(uint4*)&Al[lrow][lcol]     = make_uint4(lp[0], lp[1], lp[2], lp[3]);
            *(uint4*)&Al[lrow][lcol + 8] = make_uint4(lp[4], lp[5], lp[6], lp[7]);
            *(uint4*)&Bh[lrow][lcol]     = make_uint4(hq[0], hq[1], hq[2], hq[3]);
            *(uint4*)&Bh[lrow][lcol + 8] = make_uint4(hq[4], hq[5], hq[6], hq[7]);
            *(uint4*)&Bl[lrow][lcol]     = make_uint4(lq[0], lq[1], lq[2], lq[3]);
            *(uint4*)&Bl[lrow][lcol + 8] = make_uint4(lq[4], lq[5], lq[6], lq[7]);
        }
        __syncthreads();

        #pragma unroll
        for (int kk = 0; kk < KC; kk += 16) {
            uint32_t ah[2][4], al[2][4];
            #pragma unroll
            for (int mt = 0; mt < 2; mt++) {
                const int rb = wm * 32 + mt * 16;
                const int cc = kk + fc;
                ah[mt][0] = *(const uint32_t*)&Ah[rb + fr][cc];
                ah[mt][1] = *(const uint32_t*)&Ah[rb + fr + 8][cc];
                ah[mt][2] = *(const uint32_t*)&Ah[rb + fr][cc + 8];
                ah[mt][3] = *(const uint32_t*)&Ah[rb + fr + 8][cc + 8];
                al[mt][0] = *(const uint32_t*)&Al[rb + fr][cc];
                al[mt][1] = *(const uint32_t*)&Al[rb + fr + 8][cc];
                al[mt][2] = *(const uint32_t*)&Al[rb + fr][cc + 8];
                al[mt][3] = *(const uint32_t*)&Al[rb + fr + 8][cc + 8];
            }
            #pragma unroll
            for (int nt = 0; nt < 8; nt++) {
                const int nb = wn * 64 + nt * 8 + fr;
                const int kcc = kk + fc;
                uint32_t bh0 = *(const uint32_t*)&Bh[nb][kcc];
                uint32_t bh1 = *(const uint32_t*)&Bh[nb][kcc + 8];
                uint32_t bl0 = *(const uint32_t*)&Bl[nb][kcc];
                uint32_t bl1 = *(const uint32_t*)&Bl[nb][kcc + 8];
                #pragma unroll
                for (int mt = 0; mt < 2; mt++) {
                    mma16816(acc[mt][nt], ah[mt], bh0, bh1);
                    mma16816(acc[mt][nt], al[mt], bh0, bh1);
                    mma16816(acc[mt][nt], ah[mt], bl0, bl1);
                }
            }
        }
    }

    #pragma unroll
    for (int mt = 0; mt < 2; mt++) {
        const int row0 = m0 + wm * 32 + mt * 16 + fr;
        const int b0r = row0 >> 11, s0 = row0 & (SQ - 1);
        const int row1 = row0 + 8;
        const int b1r = row1 >> 11, s1 = row1 & (SQ - 1);
        #pragma unroll
        for (int nt = 0; nt < 8; nt++) {
            const int col = n0 + wn * 64 + nt * 8 + fc;
            const int h = col >> 6, dd = col & 63;
            const float bz0 = bias[col], bz1 = bias[col + 1];
            float* p0 = dst + ((size_t)(b0r * NH + h) * SQ + s0) * HD + dd;
            float* p1 = dst + ((size_t)(b1r * NH + h) * SQ + s1) * HD + dd;
            *(float2*)p0 = make_float2(acc[mt][nt][0] + bz0, acc[mt][nt][1] + bz1);
            *(float2*)p1 = make_float2(acc[mt][nt][2] + bz0, acc[mt][nt][3] + bz1);
        }
    }
}

// ============================================================================
// Flash attention via mma.sync fp16.
// CTA = 128 q-rows x full KV loop; 8 warps, each an m16 band.
// QK^T: single fp16 MMA (score err ~2.4e-4).
// PV:   3-MMA hi/lo split fp16 (PhVh + PlVh + PhVl, err ~1e-6).
// P accumulators repacked to A-fragments in registers.
// ============================================================================
#define BQ 128
#define BK 64
#define VP 72   // smem pitch in halves (conflict-free ldmatrix)

__global__ __launch_bounds__(256, 2) void flash_attn_mma(
    const float* __restrict__ mask, float* __restrict__ out)
{
    __shared__ __align__(16) __half Kh[BK][VP];
    __shared__ __align__(16) __half Vh[BK][VP];
    __shared__ __align__(16) __half Vl[BK][VP];

    const int tid = threadIdx.x;
    const int wid = tid >> 5, lane = tid & 31;
    const int fr = lane >> 2, fc = (lane & 3) * 2;
    const int bh = blockIdx.y;
    const int b = bh >> 4, h = bh & 15;
    const int q0 = blockIdx.x * BQ;
    const int qrow = q0 + wid * 16;

    const float* Qg = g_q + (size_t)bh * SQ * HD;
    const float* Kg = g_k + (size_t)bh * SQ * HD;
    const float* Vg = g_v + (size_t)bh * SQ * HD;
    const float* mrow = mask + (size_t)b * SQ;

    const uint32_t kh_b = smem_u32(&Kh[0][0]);
    const uint32_t vh_b = smem_u32(&Vh[0][0]);
    const uint32_t vl_b = smem_u32(&Vl[0][0]);

    // ---- Q fragments (scale 1/8 folded in), built directly from gmem ----
    uint32_t qf[4][4];
    #pragma unroll
    for (int kc = 0; kc < 4; kc++) {
        #pragma unroll
        for (int rr = 0; rr < 2; rr++) {
            const float* p = Qg + (size_t)(qrow + fr + rr * 8) * HD + kc * 16 + fc;
            float2 v0 = *(const float2*)p;
            float2 v1 = *(const float2*)(p + 8);
            qf[kc][rr]     = h2bits(__floats2half2_rn(v0.x * 0.125f, v0.y * 0.125f));
            qf[kc][rr + 2] = h2bits(__floats2half2_rn(v1.x * 0.125f, v1.y * 0.125f));
        }
    }

    float accO[8][4];
    #pragma unroll
    for (int j = 0; j < 8; j++)
        #pragma unroll
        for (int i = 0; i < 4; i++) accO[j][i] = 0.f;
    float m0r = -1e30f, m1r = -1e30f, l0 = 0.f, l1 = 0.f;

    const int lr = tid >> 2;            // KV load row 0..63
    const int lc = (tid & 3) * 16;      // KV load col base

    for (int j0 = 0; j0 < SQ; j0 += BK) {
        // ---- stage K/V tile through registers, then smem ----
        float kf[16], vf[16];
        {
            const float* kp = Kg + (size_t)(j0 + lr) * HD + lc;
            const float* vp = Vg + (size_t)(j0 + lr) * HD + lc;
            #pragma unroll
            for (int j = 0; j < 4; j++) {
                float4 t = *(const float4*)(kp + 4 * j);
                kf[4*j] = t.x; kf[4*j+1] = t.y; kf[4*j+2] = t.z; kf[4*j+3] = t.w;
                float4 u = *(const float4*)(vp + 4 * j);
                vf[4*j] = u.x; vf[4*j+1] = u.y; vf[4*j+2] = u.z; vf[4*j+3] = u.w;
            }
        }
        __syncthreads();   // previous iteration's ldmatrix reads complete
        {
            uint32_t kp8[8], vhp[8], vlp[8];
            #pragma unroll
            for (int j = 0; j < 8; j++) {
                kp8[j] = h2bits(__floats2half2_rn(kf[2*j], kf[2*j+1]));
                __half2 vh2 = __floats2half2_rn(vf[2*j], vf[2*j+1]);
                vhp[j] = h2bits(vh2);
                vlp[j] = h2bits(__floats2half2_rn(
                    vf[2*j]   - __low2float(vh2),
                    vf[2*j+1] - __high2float(vh2)));
            }
            *(uint4*)&Kh[lr][lc]     = make_uint4(kp8[0], kp8[1], kp8[2], kp8[3]);
            *(uint4*)&Kh[lr][lc + 8] = make_uint4(kp8[4], kp8[5], kp8[6], kp8[7]);
            *(uint4*)&Vh[lr][lc]     = make_uint4(vhp[0], vhp[1], vhp[2], vhp[3]);
            *(uint4*)&Vh[lr][lc + 8] = make_uint4(vhp[4], vhp[5], vhp[6], vhp[7]);
            *(uint4*)&Vl[lr][lc]     = make_uint4(vlp[0], vlp[1], vlp[2], vlp[3]);
            *(uint4*)&Vl[lr][lc + 8] = make_uint4(vlp[4], vlp[5], vlp[6], vlp[7]);
        }
        __syncthreads();

        // ---- S = Q K^T : 8 n8-tiles per warp, fp16 single ----
        float sacc[8][4];
        #pragma unroll
        for (int j = 0; j < 8; j++)
            #pragma unroll
            for (int i = 0; i < 4; i++) sacc[j][i] = 0.f;

        const int lrow16 = lane & 15;
        const int chalf = (lane & 16) >> 1;
        #pragma unroll
        for (int kc = 0; kc < 4; kc++) {
            #pragma unroll
            for (int g = 0; g < 4; g++) {
                uint32_t r0, r1, r2, r3;
                uint32_t addr = kh_b +
                    ((g * 16 + lrow16) * VP + kc * 16 + chalf) * 2;
                ldsm_x4(r0, r1, r2, r3, addr);
                mma16816h(sacc[2*g],     qf[kc], r0, r2);
                mma16816h(sacc[2*g + 1], qf[kc], r1, r3);
            }
        }

        // ---- mask + online softmax ----
        #pragma unroll
        for (int j = 0; j < 8; j++) {
            float2 mv = *(const float2*)(mrow + j0 + j * 8 + fc);
            sacc[j][0] += mv.x; sacc[j][1] += mv.y;
            sacc[j][2] += mv.x; sacc[j][3] += mv.y;
        }
        float rmax0 = -1e30f, rmax1 = -1e30f;
        #pragma unroll
        for (int j = 0; j < 8; j++) {
            rmax0 = fmaxf(rmax0, fmaxf(sacc[j][0], sacc[j][1]));
            rmax1 = fmaxf(rmax1, fmaxf(sacc[j][2], sacc[j][3]));
        }
        rmax0 = fmaxf(rmax0, __shfl_xor_sync(0xffffffffu, rmax0, 1));
        rmax0 = fmaxf(rmax0, __shfl_xor_sync(0xffffffffu, rmax0, 2));
        rmax1 = fmaxf(rmax1, __shfl_xor_sync(0xffffffffu, rmax1, 1));
        rmax1 = fmaxf(rmax1, __shfl_xor_sync(0xffffffffu, rmax1, 2));

        const float mn0 = fmaxf(m0r, rmax0);
        const float mn1 = fmaxf(m1r, rmax1);
        const float a0 = __expf(m0r - mn0);
        const float a1 = __expf(m1r - mn1);
        m0r = mn0; m1r = mn1;

        float ps0 = 0.f, ps1 = 0.f;
        uint32_t ph[16], pl[16];
        #pragma unroll
        for (int j = 0; j < 8; j++) {
            float p0 = __expf(sacc[j][0] - mn0);
            float p1 = __expf(sacc[j][1] - mn0);
            float p2 = __expf(sacc[j][2] - mn1);
            float p3 = __expf(sacc[j][3] - mn1);
            ps0 += p0 + p1;
            ps1 += p2 + p3;
            __half2 h0 = __floats2half2_rn(p0, p1);
            __half2 h1 = __floats2half2_rn(p2, p3);
            ph[2*j]   = h2bits(h0);
            ph[2*j+1] = h2bits(h1);
            pl[2*j]   = h2bits(__floats2half2_rn(p0 - __low2float(h0),
                                                 p1 - __high2float(h0)));
            pl[2*j+1] = h2bits(__floats2half2_rn(p2 - __low2float(h1),
                                                 p3 - __high2float(h1)));
        }
        l0 = l0 * a0 + ps0;
        l1 = l1 * a1 + ps1;
        #pragma unroll
        for (int j = 0; j < 8; j++) {
            accO[j][0] *= a0; accO[j][1] *= a0;
            accO[j][2] *= a1; accO[j][3] *= a1;
        }

        // ---- O += P V : split fp16, V^T via ldmatrix.trans ----
        #pragma unroll
        for (int kc = 0; kc < 4; kc++) {
            uint32_t pah[4] = { ph[4*kc], ph[4*kc+1], ph[4*kc+2], ph[4*kc+3] };
            uint32_t pal[4] = { pl[4*kc], pl[4*kc+1], pl[4*kc+2], pl[4*kc+3] };
            #pragma unroll
            for (int dg = 0; dg < 4; dg++) {
                uint32_t off = ((kc * 16 + lrow16) * VP + dg * 16 + chalf) * 2;
                uint32_t h0, h1, h2, h3, e0, e1, e2, e3;
                ldsm_x4_t(h0, h1, h2, h3, vh_b + off);
                ldsm_x4_t(e0, e1, e2, e3, vl_b + off);
                mma16816h(accO[2*dg],     pah, h0, h1);
                mma16816h(accO[2*dg],     pal, h0, h1);
                mma16816h(accO[2*dg],     pah, e0, e1);
                mma16816h(accO[2*dg + 1], pah, h2, h3);
                mma16816h(accO[2*dg + 1], pal, h2, h3);
                mma16816h(accO[2*dg + 1], pah, e2, e3);
            }
        }
    }

    // ---- epilogue: finish l reduction, normalize, write [B, S, H*d] ----
    l0 += __shfl_xor_sync(0xffffffffu, l0, 1);
    l0 += __shfl_xor_sync(0xffffffffu, l0, 2);
    l1 += __shfl_xor_sync(0xffffffffu, l1, 1);
    l1 += __shfl_xor_sync(0xffffffffu, l1, 2);
    const float inv0 = 1.0f / l0, inv1 = 1.0f / l1;

    const int s0 = qrow + fr, s1 = s0 + 8;
    float* o0 = out + ((size_t)b * SQ + s0) * DM + h * HD;
    float* o1 = out + ((size_t)b * SQ + s1) * DM + h * HD;
    #pragma unroll
    for (int dt = 0; dt < 8; dt++) {
        const int d = dt * 8 + fc;
        *(float2*)(o0 + d) = make_float2(accO[dt][0] * inv0, accO[dt][1] * inv0);
        *(float2*)(o1 + d) = make_float2(accO[dt][2] * inv1, accO[dt][3] * inv1);
    }
}

extern "C" void kernel_launch(void* const* d_in, const int* in_sizes, int n_in,
                              void* d_out, int out_size)
{
    const float* X   = (const float*)d_in[0];
    const float* Mk  = (const float*)d_in[1];
    const float* Wq  = (const float*)d_in[2];
    const float* bq  = (const float*)d_in[3];
    const float* Wk  = (const float*)d_in[4];
    const float* bk  = (const float*)d_in[5];
    const float* Wv  = (const float*)d_in[6];
    const float* bv  = (const float*)d_in[7];
    float* out = (float*)d_out;

    qkv_gemm_mma<<<dim3(8, 64, 3), 256>>>(X, Wq, bq, Wk, bk, Wv, bv);
    flash_attn_mma<<<dim3(SQ / BQ, NB * NH), 256>>>(Mk, out);
}

// round 7
// speedup vs baseline: 4.3862x; 2.1063x over previous
#include <cuda_runtime.h>
#include <cuda_fp16.h>
#include <cstdint>

#define SQ 2048
#define NB 4
#define NH 16
#define HD 64
#define DM 1024

// Scratch for Q/K/V in [B, H, S, d] layout (allocation-guard-safe device globals)
__device__ float g_q[NB * NH * SQ * HD];
__device__ float g_k[NB * NH * SQ * HD];
__device__ float g_v[NB * NH * SQ * HD];

// ---- mma.sync m16n8k16 fp16 (compute_103-legal; lowers to HMMA on sm_103a) ----
__device__ __forceinline__ void mma16816h(float* d, const uint32_t* a,
                                          uint32_t b0, uint32_t b1) {
    asm volatile(
        "mma.sync.aligned.m16n8k16.row.col.f32.f16.f16.f32 "
        "{%0,%1,%2,%3}, {%4,%5,%6,%7}, {%8,%9}, {%0,%1,%2,%3};"
        : "+f"(d[0]), "+f"(d[1]), "+f"(d[2]), "+f"(d[3])
        : "r"(a[0]), "r"(a[1]), "r"(a[2]), "r"(a[3]), "r"(b0), "r"(b1));
}
__device__ __forceinline__ uint32_t smem_u32(const void* p) {
    uint32_t a;
    asm("{ .reg .u64 t; cvta.to.shared.u64 t, %1; cvt.u32.u64 %0, t; }" : "=r"(a) : "l"(p));
    return a;
}
__device__ __forceinline__ void ldsm_x4(uint32_t& r0, uint32_t& r1, uint32_t& r2,
                                        uint32_t& r3, uint32_t addr) {
    asm volatile("ldmatrix.sync.aligned.m8n8.x4.shared.b16 {%0,%1,%2,%3}, [%4];"
                 : "=r"(r0), "=r"(r1), "=r"(r2), "=r"(r3) : "r"(addr));
}
__device__ __forceinline__ void ldsm_x4_t(uint32_t& r0, uint32_t& r1, uint32_t& r2,
                                          uint32_t& r3, uint32_t addr) {
    asm volatile("ldmatrix.sync.aligned.m8n8.x4.trans.shared.b16 {%0,%1,%2,%3}, [%4];"
                 : "=r"(r0), "=r"(r1), "=r"(r2), "=r"(r3) : "r"(addr));
}
__device__ __forceinline__ uint32_t h2bits(__half2 h) { return *(uint32_t*)&h; }

// ============================================================================
// QKV projection via mma.sync fp16-single: out = X @ W^T + b, into [B,H,S,d].
// CTA 128(M) x 128(N), K chunk 32. 8 warps = 4(M) x 2(N), warp tile 32x64.
// fp32 accumulation in the MMA; fp16 operand quantization only (~1.4e-4).
// ============================================================================
#define KC 32
#define APITCH 40

__global__ __launch_bounds__(256) void qkv_gemm_mma(
    const float* __restrict__ X,
    const float* __restrict__ Wq, const float* __restrict__ bq,
    const float* __restrict__ Wk, const float* __restrict__ bk,
    const float* __restrict__ Wv, const float* __restrict__ bv)
{
    __shared__ __align__(16) __half Ah[128][APITCH];
    __shared__ __align__(16) __half Bh[128][APITCH];

    const int z = blockIdx.z;
    const float* W    = (z == 0) ? Wq : (z == 1) ? Wk : Wv;
    const float* bias = (z == 0) ? bq : (z == 1) ? bk : bv;
    float* dst        = (z == 0) ? g_q : (z == 1) ? g_k : g_v;

    const int tid = threadIdx.x;
    const int wid = tid >> 5, lane = tid & 31;
    const int wm = wid & 3, wn = wid >> 2;
    const int m0 = blockIdx.y * 128, n0 = blockIdx.x * 128;

    const int lrow = tid >> 1;
    const int lcol = (tid & 1) * 16;
    const float* Ap = X + (size_t)(m0 + lrow) * DM + lcol;
    const float* Bp = W + (size_t)(n0 + lrow) * DM + lcol;

    float acc[2][8][4];
    #pragma unroll
    for (int mt = 0; mt < 2; mt++)
        #pragma unroll
        for (int nt = 0; nt < 8; nt++)
            #pragma unroll
            for (int j = 0; j < 4; j++) acc[mt][nt][j] = 0.f;

    const int fr = lane >> 2;
    const int fc = (lane & 3) * 2;

    for (int c = 0; c < DM / KC; c++) {
        const int k0 = c * KC;
        float va[16], vb[16];
        #pragma unroll
        for (int j = 0; j < 4; j++) {
            float4 t = *(const float4*)(Ap + k0 + j * 4);
            va[4*j] = t.x; va[4*j+1] = t.y; va[4*j+2] = t.z; va[4*j+3] = t.w;
            float4 u = *(const float4*)(Bp + k0 + j * 4);
            vb[4*j] = u.x; vb[4*j+1] = u.y; vb[4*j+2] = u.z; vb[4*j+3] = u.w;
        }
        __syncthreads();
        {
            uint32_t hp[8], hq[8];
            #pragma unroll
            for (int j = 0; j < 8; j++) {
                hp[j] = h2bits(__floats2half2_rn(va[2*j], va[2*j+1]));
                hq[j] = h2bits(__floats2half2_rn(vb[2*j], vb[2*j+1]));
            }
            *(uint4*)&Ah[lrow][lcol]     = make_uint4(hp[0], hp[1], hp[2], hp[3]);
            *(uint4*)&Ah[lrow][lcol + 8] = make_uint4(hp[4], hp[5], hp[6], hp[7]);
            *(uint4*)&Bh[lrow][lcol]     = make_uint4(hq[0], hq[1], hq[2], hq[3]);
            *(uint4*)&Bh[lrow][lcol + 8] = make_uint4(hq[4], hq[5], hq[6], hq[7]);
        }
        __syncthreads();

        #pragma unroll
        for (int kk = 0; kk < KC; kk += 16) {
            uint32_t ah[2][4];
            #pragma unroll
            for (int mt = 0; mt < 2; mt++) {
                const int rb = wm * 32 + mt * 16;
                const int cc = kk + fc;
                ah[mt][0] = *(const uint32_t*)&Ah[rb + fr][cc];
                ah[mt][1] = *(const uint32_t*)&Ah[rb + fr + 8][cc];
                ah[mt][2] = *(const uint32_t*)&Ah[rb + fr][cc + 8];
                ah[mt][3] = *(const uint32_t*)&Ah[rb + fr + 8][cc + 8];
            }
            #pragma unroll
            for (int nt = 0; nt < 8; nt++) {
                const int nb = wn * 64 + nt * 8 + fr;
                const int kcc = kk + fc;
                uint32_t bh0 = *(const uint32_t*)&Bh[nb][kcc];
                uint32_t bh1 = *(const uint32_t*)&Bh[nb][kcc + 8];
                mma16816h(acc[0][nt], ah[0], bh0, bh1);
                mma16816h(acc[1][nt], ah[1], bh0, bh1);
            }
        }
    }

    #pragma unroll
    for (int mt = 0; mt < 2; mt++) {
        const int row0 = m0 + wm * 32 + mt * 16 + fr;
        const int b0r = row0 >> 11, s0 = row0 & (SQ - 1);
        const int row1 = row0 + 8;
        const int b1r = row1 >> 11, s1 = row1 & (SQ - 1);
        #pragma unroll
        for (int nt = 0; nt < 8; nt++) {
            const int col = n0 + wn * 64 + nt * 8 + fc;
            const int h = col >> 6, dd = col & 63;
            const float bz0 = bias[col], bz1 = bias[col + 1];
            float* p0 = dst + ((size_t)(b0r * NH + h) * SQ + s0) * HD + dd;
            float* p1 = dst + ((size_t)(b1r * NH + h) * SQ + s1) * HD + dd;
            *(float2*)p0 = make_float2(acc[mt][nt][0] + bz0, acc[mt][nt][1] + bz1);
            *(float2*)p1 = make_float2(acc[mt][nt][2] + bz0, acc[mt][nt][3] + bz1);
        }
    }
}

// ============================================================================
// Flash attention via mma.sync fp16-single (QK^T and PV, fp32 accum).
// CTA = 128 q-rows x full KV loop; 8 warps, each an m16 band.
// ============================================================================
#define BQ 128
#define BK 64
#define VP 72   // smem pitch in halves (conflict-free ldmatrix)

__global__ __launch_bounds__(256, 2) void flash_attn_mma(
    const float* __restrict__ mask, float* __restrict__ out)
{
    __shared__ __align__(16) __half Kh[BK][VP];
    __shared__ __align__(16) __half Vh[BK][VP];

    const int tid = threadIdx.x;
    const int wid = tid >> 5, lane = tid & 31;
    const int fr = lane >> 2, fc = (lane & 3) * 2;
    const int bh = blockIdx.y;
    const int b = bh >> 4, h = bh & 15;
    const int q0 = blockIdx.x * BQ;
    const int qrow = q0 + wid * 16;

    const float* Qg = g_q + (size_t)bh * SQ * HD;
    const float* Kg = g_k + (size_t)bh * SQ * HD;
    const float* Vg = g_v + (size_t)bh * SQ * HD;
    const float* mrow = mask + (size_t)b * SQ;

    const uint32_t kh_b = smem_u32(&Kh[0][0]);
    const uint32_t vh_b = smem_u32(&Vh[0][0]);

    // ---- Q fragments (scale 1/8 folded in), built directly from gmem ----
    uint32_t qf[4][4];
    #pragma unroll
    for (int kc = 0; kc < 4; kc++) {
        #pragma unroll
        for (int rr = 0; rr < 2; rr++) {
            const float* p = Qg + (size_t)(qrow + fr + rr * 8) * HD + kc * 16 + fc;
            float2 v0 = *(const float2*)p;
            float2 v1 = *(const float2*)(p + 8);
            qf[kc][rr]     = h2bits(__floats2half2_rn(v0.x * 0.125f, v0.y * 0.125f));
            qf[kc][rr + 2] = h2bits(__floats2half2_rn(v1.x * 0.125f, v1.y * 0.125f));
        }
    }

    float accO[8][4];
    #pragma unroll
    for (int j = 0; j < 8; j++)
        #pragma unroll
        for (int i = 0; i < 4; i++) accO[j][i] = 0.f;
    float m0r = -1e30f, m1r = -1e30f, l0 = 0.f, l1 = 0.f;

    const int lr = tid >> 2;            // KV load row 0..63
    const int lc = (tid & 3) * 16;      // KV load col base

    for (int j0 = 0; j0 < SQ; j0 += BK) {
        // ---- stage K/V tile through registers, then smem ----
        float kf[16], vf[16];
        {
            const float* kp = Kg + (size_t)(j0 + lr) * HD + lc;
            const float* vp = Vg + (size_t)(j0 + lr) * HD + lc;
            #pragma unroll
            for (int j = 0; j < 4; j++) {
                float4 t = *(const float4*)(kp + 4 * j);
                kf[4*j] = t.x; kf[4*j+1] = t.y; kf[4*j+2] = t.z; kf[4*j+3] = t.w;
                float4 u = *(const float4*)(vp + 4 * j);
                vf[4*j] = u.x; vf[4*j+1] = u.y; vf[4*j+2] = u.z; vf[4*j+3] = u.w;
            }
        }
        __syncthreads();   // previous iteration's ldmatrix reads complete
        {
            uint32_t kp8[8], vhp[8];
            #pragma unroll
            for (int j = 0; j < 8; j++) {
                kp8[j] = h2bits(__floats2half2_rn(kf[2*j], kf[2*j+1]));
                vhp[j] = h2bits(__floats2half2_rn(vf[2*j], vf[2*j+1]));
            }
            *(uint4*)&Kh[lr][lc]     = make_uint4(kp8[0], kp8[1], kp8[2], kp8[3]);
            *(uint4*)&Kh[lr][lc + 8] = make_uint4(kp8[4], kp8[5], kp8[6], kp8[7]);
            *(uint4*)&Vh[lr][lc]     = make_uint4(vhp[0], vhp[1], vhp[2], vhp[3]);
            *(uint4*)&Vh[lr][lc + 8] = make_uint4(vhp[4], vhp[5], vhp[6], vhp[7]);
        }
        __syncthreads();

        // ---- S = Q K^T : 8 n8-tiles per warp ----
        float sacc[8][4];
        #pragma unroll
        for (int j = 0; j < 8; j++)
            #pragma unroll
            for (int i = 0; i < 4; i++) sacc[j][i] = 0.f;

        const int lrow16 = lane & 15;
        const int chalf = (lane & 16) >> 1;
        #pragma unroll
        for (int kc = 0; kc < 4; kc++) {
            #pragma unroll
            for (int g = 0; g < 4; g++) {
                uint32_t r0, r1, r2, r3;
                uint32_t addr = kh_b +
                    ((g * 16 + lrow16) * VP + kc * 16 + chalf) * 2;
                ldsm_x4(r0, r1, r2, r3, addr);
                mma16816h(sacc[2*g],     qf[kc], r0, r2);
                mma16816h(sacc[2*g + 1], qf[kc], r1, r3);
            }
        }

        // ---- mask + online softmax ----
        #pragma unroll
        for (int j = 0; j < 8; j++) {
            float2 mv = *(const float2*)(mrow + j0 + j * 8 + fc);
            sacc[j][0] += mv.x; sacc[j][1] += mv.y;
            sacc[j][2] += mv.x; sacc[j][3] += mv.y;
        }
        float rmax0 = -1e30f, rmax1 = -1e30f;
        #pragma unroll
        for (int j = 0; j < 8; j++) {
            rmax0 = fmaxf(rmax0, fmaxf(sacc[j][0], sacc[j][1]));
            rmax1 = fmaxf(rmax1, fmaxf(sacc[j][2], sacc[j][3]));
        }
        rmax0 = fmaxf(rmax0, __shfl_xor_sync(0xffffffffu, rmax0, 1));
        rmax0 = fmaxf(rmax0, __shfl_xor_sync(0xffffffffu, rmax0, 2));
        rmax1 = fmaxf(rmax1, __shfl_xor_sync(0xffffffffu, rmax1, 1));
        rmax1 = fmaxf(rmax1, __shfl_xor_sync(0xffffffffu, rmax1, 2));

        const float mn0 = fmaxf(m0r, rmax0);
        const float mn1 = fmaxf(m1r, rmax1);
        const float a0 = __expf(m0r - mn0);
        const float a1 = __expf(m1r - mn1);
        m0r = mn0; m1r = mn1;

        float ps0 = 0.f, ps1 = 0.f;
        uint32_t ph[16];
        #pragma unroll
        for (int j = 0; j < 8; j++) {
            float p0 = __expf(sacc[j][0] - mn0);
            float p1 = __expf(sacc[j][1] - mn0);
            float p2 = __expf(sacc[j][2] - mn1);
            float p3 = __expf(sacc[j][3] - mn1);
            ps0 += p0 + p1;
            ps1 += p2 + p3;
            ph[2*j]   = h2bits(__floats2half2_rn(p0, p1));
            ph[2*j+1] = h2bits(__floats2half2_rn(p2, p3));
        }
        l0 = l0 * a0 + ps0;
        l1 = l1 * a1 + ps1;
        #pragma unroll
        for (int j = 0; j < 8; j++) {
            accO[j][0] *= a0; accO[j][1] *= a0;
            accO[j][2] *= a1; accO[j][3] *= a1;
        }

        // ---- O += P V : fp16 single, V^T via ldmatrix.trans ----
        #pragma unroll
        for (int kc = 0; kc < 4; kc++) {
            uint32_t pah[4] = { ph[4*kc], ph[4*kc+1], ph[4*kc+2], ph[4*kc+3] };
            #pragma unroll
            for (int dg = 0; dg < 4; dg++) {
                uint32_t off = ((kc * 16 + lrow16) * VP + dg * 16 + chalf) * 2;
                uint32_t h0, h1, h2, h3;
                ldsm_x4_t(h0, h1, h2, h3, vh_b + off);
                mma16816h(accO[2*dg],     pah, h0, h1);
                mma16816h(accO[2*dg + 1], pah, h2, h3);
            }
        }
    }

    // ---- epilogue: finish l reduction, normalize, write [B, S, H*d] ----
    l0 += __shfl_xor_sync(0xffffffffu, l0, 1);
    l0 += __shfl_xor_sync(0xffffffffu, l0, 2);
    l1 += __shfl_xor_sync(0xffffffffu, l1, 1);
    l1 += __shfl_xor_sync(0xffffffffu, l1, 2);
    const float inv0 = 1.0f / l0, inv1 = 1.0f / l1;

    const int s0 = qrow + fr, s1 = s0 + 8;
    float* o0 = out + ((size_t)b * SQ + s0) * DM + h * HD;
    float* o1 = out + ((size_t)b * SQ + s1) * DM + h * HD;
    #pragma unroll
    for (int dt = 0; dt < 8; dt++) {
        const int d = dt * 8 + fc;
        *(float2*)(o0 + d) = make_float2(accO[dt][0] * inv0, accO[dt][1] * inv0);
        *(float2*)(o1 + d) = make_float2(accO[dt][2] * inv1, accO[dt][3] * inv1);
    }
}

extern "C" void kernel_launch(void* const* d_in, const int* in_sizes, int n_in,
                              void* d_out, int out_size)
{
    const float* X   = (const float*)d_in[0];
    const float* Mk  = (const float*)d_in[1];
    const float* Wq  = (const float*)d_in[2];
    const float* bq  = (const float*)d_in[3];
    const float* Wk  = (const float*)d_in[4];
    const float* bk  = (const float*)d_in[5];
    const float* Wv  = (const float*)d_in[6];
    const float* bv  = (const float*)d_in[7];
    float* out = (float*)d_out;

    qkv_gemm_mma<<<dim3(8, 64, 3), 256>>>(X, Wq, bq, Wk, bk, Wv, bv);
    flash_attn_mma<<<dim3(SQ / BQ, NB * NH), 256>>>(Mk, out);
}

// round 9
// speedup vs baseline: 6.1891x; 1.4111x over previous
#include <cuda_runtime.h>
#include <cuda_fp16.h>
#include <cstdint>

#define SQ 2048
#define NB 4
#define NH 16
#define HD 64
#define DM 1024

// fp16 persistent tensors (allocation-guard-safe device globals)
__device__ __half g_xh[NB * SQ * DM];          // X in fp16
__device__ __half g_wh[3 * DM * DM];           // Wq|Wk|Wv in fp16
__device__ __half g_qh[NB * NH * SQ * HD];     // q (pre-scaled by 1/8)
__device__ __half g_kh[NB * NH * SQ * HD];
__device__ __half g_vh[NB * NH * SQ * HD];

// ---- mma.sync m16n8k16 fp16 ----
__device__ __forceinline__ void mma16816h(float* d, const uint32_t* a,
                                          uint32_t b0, uint32_t b1) {
    asm volatile(
        "mma.sync.aligned.m16n8k16.row.col.f32.f16.f16.f32 "
        "{%0,%1,%2,%3}, {%4,%5,%6,%7}, {%8,%9}, {%0,%1,%2,%3};"
        : "+f"(d[0]), "+f"(d[1]), "+f"(d[2]), "+f"(d[3])
        : "r"(a[0]), "r"(a[1]), "r"(a[2]), "r"(a[3]), "r"(b0), "r"(b1));
}
__device__ __forceinline__ uint32_t smem_u32(const void* p) {
    uint32_t a;
    asm("{ .reg .u64 t; cvta.to.shared.u64 t, %1; cvt.u32.u64 %0, t; }" : "=r"(a) : "l"(p));
    return a;
}
__device__ __forceinline__ void ldsm_x4(uint32_t& r0, uint32_t& r1, uint32_t& r2,
                                        uint32_t& r3, uint32_t addr) {
    asm volatile("ldmatrix.sync.aligned.m8n8.x4.shared.b16 {%0,%1,%2,%3}, [%4];"
                 : "=r"(r0), "=r"(r1), "=r"(r2), "=r"(r3) : "r"(addr));
}
__device__ __forceinline__ void ldsm_x4_t(uint32_t& r0, uint32_t& r1, uint32_t& r2,
                                          uint32_t& r3, uint32_t addr) {
    asm volatile("ldmatrix.sync.aligned.m8n8.x4.trans.shared.b16 {%0,%1,%2,%3}, [%4];"
                 : "=r"(r0), "=r"(r1), "=r"(r2), "=r"(r3) : "r"(addr));
}
__device__ __forceinline__ uint32_t h2bits(__half2 h) { return *(uint32_t*)&h; }

// ---- cp.async (sm_80 baseline; legal at compute_103) ----
#define CP16(sm, gp) asm volatile("cp.async.cg.shared.global [%0], [%1], 16;" \
                                  :: "r"(sm), "l"(gp))
#define CP_COMMIT()  asm volatile("cp.async.commit_group;" ::: "memory")
#define CP_WAIT1()   asm volatile("cp.async.wait_group 1;" ::: "memory")
#define CP_WAIT0()   asm volatile("cp.async.wait_group 0;" ::: "memory")

// ============================================================================
// fp32 -> fp16 convert (one-time, memory-bound). which: 0=X, 1..3=Wq/Wk/Wv
// ============================================================================
__global__ __launch_bounds__(256) void cvt_f16(const float* __restrict__ src,
                                               int which, int n)
{
    __half* dst = (which == 0) ? g_xh : g_wh + (size_t)(which - 1) * DM * DM;
    const int i = (blockIdx.x * 256 + threadIdx.x) * 8;
    if (i >= n) return;
    float4 a = *(const float4*)(src + i);
    float4 b = *(const float4*)(src + i + 4);
    uint32_t p0 = h2bits(__floats2half2_rn(a.x, a.y));
    uint32_t p1 = h2bits(__floats2half2_rn(a.z, a.w));
    uint32_t p2 = h2bits(__floats2half2_rn(b.x, b.y));
    uint32_t p3 = h2bits(__floats2half2_rn(b.z, b.w));
    *(uint4*)(dst + i) = make_uint4(p0, p1, p2, p3);
}

// ============================================================================
// QKV projection, fp16 in/out: dst = fp16((X @ W^T + b) * s), s=1/8 for q.
// CTA 128x128, KC=32, double-buffered cp.async, ldmatrix fragments.
// 8 warps = 4(M) x 2(N); warp tile 32x64.
// Each staging thread covers 16 halves (2 x 16B cp.async): full 32-half rows.
// ============================================================================
#define KCH 32

__global__ __launch_bounds__(256, 2) void qkv_gemm_f16(
    const float* __restrict__ bq, const float* __restrict__ bk,
    const float* __restrict__ bv)
{
    __shared__ __align__(16) __half As[2][128][40];
    __shared__ __align__(16) __half Bs[2][128][40];

    const int z = blockIdx.z;
    const float* bias = (z == 0) ? bq : (z == 1) ? bk : bv;
    __half* dst       = (z == 0) ? g_qh : (z == 1) ? g_kh : g_vh;
    const __half* Wp  = g_wh + (size_t)z * DM * DM;

    const int tid = threadIdx.x;
    const int wid = tid >> 5, lane = tid & 31;
    const int wm = wid & 3, wn = wid >> 2;
    const int m0 = blockIdx.y * 128, n0 = blockIdx.x * 128;

    const int lrow = tid >> 1;            // 0..127
    const int lck = (tid & 1) * 16;       // half-offset: 0 or 16
    const __half* Ag = g_xh + (size_t)(m0 + lrow) * DM + lck;
    const __half* Bg = Wp + (size_t)(n0 + lrow) * DM + lck;

    float acc[2][8][4];
    #pragma unroll
    for (int mt = 0; mt < 2; mt++)
        #pragma unroll
        for (int nt = 0; nt < 8; nt++)
            #pragma unroll
            for (int j = 0; j < 4; j++) acc[mt][nt][j] = 0.f;

    const int fr = lane >> 2, fc = (lane & 3) * 2;
    const int lrow16 = lane & 15;
    const int chalf = (lane & 16) >> 1;   // 0 or 8 halves

    // prologue: stage chunk 0 (two 16B copies per tensor = 16 halves/thread)
    CP16(smem_u32(&As[0][lrow][lck]),     Ag);
    CP16(smem_u32(&As[0][lrow][lck + 8]), Ag + 8);
    CP16(smem_u32(&Bs[0][lrow][lck]),     Bg);
    CP16(smem_u32(&Bs[0][lrow][lck + 8]), Bg + 8);
    CP_COMMIT();

    const int NCH = DM / KCH;   // 32
    for (int c = 0; c < NCH; c++) {
        if (c + 1 < NCH) {
            const int nb = (c + 1) & 1;
            const __half* An = Ag + (c + 1) * KCH;
            const __half* Bn = Bg + (c + 1) * KCH;
            CP16(smem_u32(&As[nb][lrow][lck]),     An);
            CP16(smem_u32(&As[nb][lrow][lck + 8]), An + 8);
            CP16(smem_u32(&Bs[nb][lrow][lck]),     Bn);
            CP16(smem_u32(&Bs[nb][lrow][lck + 8]), Bn + 8);
            CP_COMMIT();
            CP_WAIT1();
        } else {
            CP_WAIT0();
        }
        __syncthreads();
        const int b = c & 1;

        #pragma unroll
        for (int kk = 0; kk < KCH; kk += 16) {
            uint32_t a[2][4];
            #pragma unroll
            for (int mt = 0; mt < 2; mt++)
                ldsm_x4(a[mt][0], a[mt][1], a[mt][2], a[mt][3],
                        smem_u32(&As[b][wm * 32 + mt * 16 + lrow16][kk + chalf]));
            #pragma unroll
            for (int g = 0; g < 4; g++) {
                uint32_t r0, r1, r2, r3;
                ldsm_x4(r0, r1, r2, r3,
                        smem_u32(&Bs[b][wn * 64 + g * 16 + lrow16][kk + chalf]));
                mma16816h(acc[0][2 * g],     a[0], r0, r2);
                mma16816h(acc[1][2 * g],     a[1], r0, r2);
                mma16816h(acc[0][2 * g + 1], a[0], r1, r3);
                mma16816h(acc[1][2 * g + 1], a[1], r1, r3);
            }
        }
        __syncthreads();   // all reads done before next issue overwrites buf
    }

    // ---- epilogue: +bias, (q: *0.125), fp16, into [B, H, S, 64] scratch ----
    const float s = (z == 0) ? 0.125f : 1.0f;
    #pragma unroll
    for (int mt = 0; mt < 2; mt++) {
        const int row0 = m0 + wm * 32 + mt * 16 + fr;
        const int b0r = row0 >> 11, s0 = row0 & (SQ - 1);
        const int row1 = row0 + 8;
        const int b1r = row1 >> 11, s1 = row1 & (SQ - 1);
        #pragma unroll
        for (int nt = 0; nt < 8; nt++) {
            const int col = n0 + wn * 64 + nt * 8 + fc;
            const int h = col >> 6, dd = col & 63;
            const float bz0 = bias[col], bz1 = bias[col + 1];
            __half* p0 = dst + ((size_t)(b0r * NH + h) * SQ + s0) * HD + dd;
            __half* p1 = dst + ((size_t)(b1r * NH + h) * SQ + s1) * HD + dd;
            *(__half2*)p0 = __floats2half2_rn((acc[mt][nt][0] + bz0) * s,
                                              (acc[mt][nt][1] + bz1) * s);
            *(__half2*)p1 = __floats2half2_rn((acc[mt][nt][2] + bz0) * s,
                                              (acc[mt][nt][3] + bz1) * s);
        }
    }
}

// ============================================================================
// Flash attention, fp16 scratch in, cp.async double-buffered K/V, no converts.
// CTA = 128 q-rows; 8 warps, each an m16 band; BK=64.
// ============================================================================
#define BQ 128
#define BK 64
#define VP 72

__global__ __launch_bounds__(256, 2) void flash_attn_mma(
    const float* __restrict__ mask, float* __restrict__ out)
{
    __shared__ __align__(16) __half KVs[2][2][BK][VP];   // [buf][K/V][row][col]

    const int tid = threadIdx.x;
    const int wid = tid >> 5, lane = tid & 31;
    const int fr = lane >> 2, fc = (lane & 3) * 2;
    const int bh = blockIdx.y;
    const int b = bh >> 4, h = bh & 15;
    const int q0 = blockIdx.x * BQ;
    const int qrow = q0 + wid * 16;

    const __half* Qg = g_qh + (size_t)bh * SQ * HD;
    const __half* Kg = g_kh + (size_t)bh * SQ * HD;
    const __half* Vg = g_vh + (size_t)bh * SQ * HD;
    const float* mrow = mask + (size_t)b * SQ;

    // ---- Q fragments: raw 32-bit loads from fp16 scratch (already scaled) ----
    uint32_t qf[4][4];
    #pragma unroll
    for (int kc = 0; kc < 4; kc++) {
        #pragma unroll
        for (int rr = 0; rr < 2; rr++) {
            const __half* p = Qg + (size_t)(qrow + fr + rr * 8) * HD + kc * 16 + fc;
            qf[kc][rr]     = *(const uint32_t*)p;
            qf[kc][rr + 2] = *(const uint32_t*)(p + 8);
        }
    }

    float accO[8][4];
    #pragma unroll
    for (int j = 0; j < 8; j++)
        #pragma unroll
        for (int i = 0; i < 4; i++) accO[j][i] = 0.f;
    float m0r = -1e30f, m1r = -1e30f, l0 = 0.f, l1 = 0.f;

    // cp.async mapping: 64 rows x 64 halves; 4 threads/row x 2 x 8 halves
    const int krow = tid >> 2;
    const int kcol = (tid & 3) * 16;      // halves

    // prologue: stage tile 0
    {
        const __half* kp = Kg + (size_t)krow * HD + kcol;
        const __half* vp = Vg + (size_t)krow * HD + kcol;
        CP16(smem_u32(&KVs[0][0][krow][kcol]),     kp);
        CP16(smem_u32(&KVs[0][0][krow][kcol + 8]), kp + 8);
        CP16(smem_u32(&KVs[0][1][krow][kcol]),     vp);
        CP16(smem_u32(&KVs[0][1][krow][kcol + 8]), vp + 8);
        CP_COMMIT();
    }

    const int lrow16 = lane & 15;
    const int chalf = (lane & 16) >> 1;
    const int NIT = SQ / BK;   // 32

    for (int it = 0; it < NIT; it++) {
        if (it + 1 < NIT) {
            const int nb = (it + 1) & 1;
            const __half* kp = Kg + (size_t)((it + 1) * BK + krow) * HD + kcol;
            const __half* vp = Vg + (size_t)((it + 1) * BK + krow) * HD + kcol;
            CP16(smem_u32(&KVs[nb][0][krow][kcol]),     kp);
            CP16(smem_u32(&KVs[nb][0][krow][kcol + 8]), kp + 8);
            CP16(smem_u32(&KVs[nb][1][krow][kcol]),     vp);
            CP16(smem_u32(&KVs[nb][1][krow][kcol + 8]), vp + 8);
            CP_COMMIT();
            CP_WAIT1();
        } else {
            CP_WAIT0();
        }
        __syncthreads();
        const int bf = it & 1;
        const uint32_t kh_b = smem_u32(&KVs[bf][0][0][0]);
        const uint32_t vh_b = smem_u32(&KVs[bf][1][0][0]);
        const int j0 = it * BK;

        // ---- S = Q K^T ----
        float sacc[8][4];
        #pragma unroll
        for (int j = 0; j < 8; j++)
            #pragma unroll
            for (int i = 0; i < 4; i++) sacc[j][i] = 0.f;

        #pragma unroll
        for (int kc = 0; kc < 4; kc++) {
            #pragma unroll
            for (int g = 0; g < 4; g++) {
                uint32_t r0, r1, r2, r3;
                uint32_t addr = kh_b +
                    ((g * 16 + lrow16) * VP + kc * 16 + chalf) * 2;
                ldsm_x4(r0, r1, r2, r3, addr);
                mma16816h(sacc[2 * g],     qf[kc], r0, r2);
                mma16816h(sacc[2 * g + 1], qf[kc], r1, r3);
            }
        }

        // ---- mask + online softmax ----
        #pragma unroll
        for (int j = 0; j < 8; j++) {
            float2 mv = *(const float2*)(mrow + j0 + j * 8 + fc);
            sacc[j][0] += mv.x; sacc[j][1] += mv.y;
            sacc[j][2] += mv.x; sacc[j][3] += mv.y;
        }
        float rmax0 = -1e30f, rmax1 = -1e30f;
        #pragma unroll
        for (int j = 0; j < 8; j++) {
            rmax0 = fmaxf(rmax0, fmaxf(sacc[j][0], sacc[j][1]));
            rmax1 = fmaxf(rmax1, fmaxf(sacc[j][2], sacc[j][3]));
        }
        rmax0 = fmaxf(rmax0, __shfl_xor_sync(0xffffffffu, rmax0, 1));
        rmax0 = fmaxf(rmax0, __shfl_xor_sync(0xffffffffu, rmax0, 2));
        rmax1 = fmaxf(rmax1, __shfl_xor_sync(0xffffffffu, rmax1, 1));
        rmax1 = fmaxf(rmax1, __shfl_xor_sync(0xffffffffu, rmax1, 2));

        const float mn0 = fmaxf(m0r, rmax0);
        const float mn1 = fmaxf(m1r, rmax1);
        const float a0 = __expf(m0r - mn0);
        const float a1 = __expf(m1r - mn1);
        m0r = mn0; m1r = mn1;

        float ps0 = 0.f, ps1 = 0.f;
        uint32_t ph[16];
        #pragma unroll
        for (int j = 0; j < 8; j++) {
            float p0 = __expf(sacc[j][0] - mn0);
            float p1 = __expf(sacc[j][1] - mn0);
            float p2 = __expf(sacc[j][2] - mn1);
            float p3 = __expf(sacc[j][3] - mn1);
            ps0 += p0 + p1;
            ps1 += p2 + p3;
            ph[2 * j]     = h2bits(__floats2half2_rn(p0, p1));
            ph[2 * j + 1] = h2bits(__floats2half2_rn(p2, p3));
        }
        l0 = l0 * a0 + ps0;
        l1 = l1 * a1 + ps1;
        #pragma unroll
        for (int j = 0; j < 8; j++) {
            accO[j][0] *= a0; accO[j][1] *= a0;
            accO[j][2] *= a1; accO[j][3] *= a1;
        }

        // ---- O += P V ----
        #pragma unroll
        for (int kc = 0; kc < 4; kc++) {
            uint32_t pah[4] = { ph[4*kc], ph[4*kc+1], ph[4*kc+2], ph[4*kc+3] };
            #pragma unroll
            for (int dg = 0; dg < 4; dg++) {
                uint32_t off = vh_b + ((kc * 16 + lrow16) * VP + dg * 16 + chalf) * 2;
                uint32_t h0, h1, h2, h3;
                ldsm_x4_t(h0, h1, h2, h3, off);
                mma16816h(accO[2 * dg],     pah, h0, h1);
                mma16816h(accO[2 * dg + 1], pah, h2, h3);
            }
        }
        __syncthreads();   // reads done before next issue overwrites buf
    }

    // ---- epilogue ----
    l0 += __shfl_xor_sync(0xffffffffu, l0, 1);
    l0 += __shfl_xor_sync(0xffffffffu, l0, 2);
    l1 += __shfl_xor_sync(0xffffffffu, l1, 1);
    l1 += __shfl_xor_sync(0xffffffffu, l1, 2);
    const float inv0 = 1.0f / l0, inv1 = 1.0f / l1;

    const int s0 = qrow + fr, s1 = s0 + 8;
    float* o0 = out + ((size_t)b * SQ + s0) * DM + h * HD;
    float* o1 = out + ((size_t)b * SQ + s1) * DM + h * HD;
    #pragma unroll
    for (int dt = 0; dt < 8; dt++) {
        const int d = dt * 8 + fc;
        *(float2*)(o0 + d) = make_float2(accO[dt][0] * inv0, accO[dt][1] * inv0);
        *(float2*)(o1 + d) = make_float2(accO[dt][2] * inv1, accO[dt][3] * inv1);
    }
}

extern "C" void kernel_launch(void* const* d_in, const int* in_sizes, int n_in,
                              void* d_out, int out_size)
{
    const float* X   = (const float*)d_in[0];
    const float* Mk  = (const float*)d_in[1];
    const float* Wq  = (const float*)d_in[2];
    const float* bq  = (const float*)d_in[3];
    const float* Wk  = (const float*)d_in[4];
    const float* bk  = (const float*)d_in[5];
    const float* Wv  = (const float*)d_in[6];
    const float* bv  = (const float*)d_in[7];
    float* out = (float*)d_out;

    cvt_f16<<<NB * SQ * DM / 2048, 256>>>(X, 0, NB * SQ * DM);
    cvt_f16<<<DM * DM / 2048, 256>>>(Wq, 1, DM * DM);
    cvt_f16<<<DM * DM / 2048, 256>>>(Wk, 2, DM * DM);
    cvt_f16<<<DM * DM / 2048, 256>>>(Wv, 3, DM * DM);
    qkv_gemm_f16<<<dim3(8, 64, 3), 256>>>(bq, bk, bv);
    flash_attn_mma<<<dim3(SQ / BQ, NB * NH), 256>>>(Mk, out);
}

// round 10
// speedup vs baseline: 6.6916x; 1.0812x over previous
#include <cuda_runtime.h>
#include <cuda_fp16.h>
#include <cstdint>

#define SQ 2048
#define NB 4
#define NH 16
#define HD 64
#define DM 1024

// fp16 persistent tensors (allocation-guard-safe device globals)
__device__ __half g_xh[NB * SQ * DM];          // X in fp16
__device__ __half g_wh[3 * DM * DM];           // Wq|Wk|Wv in fp16
__device__ __half g_qh[NB * NH * SQ * HD];     // q (pre-scaled by 1/8)
__device__ __half g_kh[NB * NH * SQ * HD];
__device__ __half g_vh[NB * NH * SQ * HD];

// ---- mma.sync m16n8k16 fp16 ----
__device__ __forceinline__ void mma16816h(float* d, const uint32_t* a,
                                          uint32_t b0, uint32_t b1) {
    asm volatile(
        "mma.sync.aligned.m16n8k16.row.col.f32.f16.f16.f32 "
        "{%0,%1,%2,%3}, {%4,%5,%6,%7}, {%8,%9}, {%0,%1,%2,%3};"
        : "+f"(d[0]), "+f"(d[1]), "+f"(d[2]), "+f"(d[3])
        : "r"(a[0]), "r"(a[1]), "r"(a[2]), "r"(a[3]), "r"(b0), "r"(b1));
}
__device__ __forceinline__ uint32_t smem_u32(const void* p) {
    uint32_t a;
    asm("{ .reg .u64 t; cvta.to.shared.u64 t, %1; cvt.u32.u64 %0, t; }" : "=r"(a) : "l"(p));
    return a;
}
__device__ __forceinline__ void ldsm_x4(uint32_t& r0, uint32_t& r1, uint32_t& r2,
                                        uint32_t& r3, uint32_t addr) {
    asm volatile("ldmatrix.sync.aligned.m8n8.x4.shared.b16 {%0,%1,%2,%3}, [%4];"
                 : "=r"(r0), "=r"(r1), "=r"(r2), "=r"(r3) : "r"(addr));
}
__device__ __forceinline__ void ldsm_x4_t(uint32_t& r0, uint32_t& r1, uint32_t& r2,
                                          uint32_t& r3, uint32_t addr) {
    asm volatile("ldmatrix.sync.aligned.m8n8.x4.trans.shared.b16 {%0,%1,%2,%3}, [%4];"
                 : "=r"(r0), "=r"(r1), "=r"(r2), "=r"(r3) : "r"(addr));
}
__device__ __forceinline__ uint32_t h2bits(__half2 h) { return *(uint32_t*)&h; }

// ---- cp.async (sm_80 baseline; legal at compute_103) ----
#define CP16(sm, gp) asm volatile("cp.async.cg.shared.global [%0], [%1], 16;" \
                                  :: "r"(sm), "l"(gp))
#define CP_COMMIT()  asm volatile("cp.async.commit_group;" ::: "memory")
#define CP_WAIT2()   asm volatile("cp.async.wait_group 2;" ::: "memory")
#define CP_WAIT1()   asm volatile("cp.async.wait_group 1;" ::: "memory")
#define CP_WAIT0()   asm volatile("cp.async.wait_group 0;" ::: "memory")

// ============================================================================
// fp32 -> fp16 converts (one-time, memory-bound)
// ============================================================================
__global__ __launch_bounds__(256) void cvt_x(const float* __restrict__ src, int n)
{
    const int i = (blockIdx.x * 256 + threadIdx.x) * 8;
    if (i >= n) return;
    float4 a = *(const float4*)(src + i);
    float4 b = *(const float4*)(src + i + 4);
    *(uint4*)(g_xh + i) = make_uint4(
        h2bits(__floats2half2_rn(a.x, a.y)), h2bits(__floats2half2_rn(a.z, a.w)),
        h2bits(__floats2half2_rn(b.x, b.y)), h2bits(__floats2half2_rn(b.z, b.w)));
}
__global__ __launch_bounds__(256) void cvt_w(const float* __restrict__ Wq,
                                             const float* __restrict__ Wk,
                                             const float* __restrict__ Wv)
{
    const int i = (blockIdx.x * 256 + threadIdx.x) * 8;   // 0 .. 3*DM*DM
    const int which = i / (DM * DM);
    const int j = i - which * (DM * DM);
    const float* src = (which == 0) ? Wq : (which == 1) ? Wk : Wv;
    float4 a = *(const float4*)(src + j);
    float4 b = *(const float4*)(src + j + 4);
    *(uint4*)(g_wh + i) = make_uint4(
        h2bits(__floats2half2_rn(a.x, a.y)), h2bits(__floats2half2_rn(a.z, a.w)),
        h2bits(__floats2half2_rn(b.x, b.y)), h2bits(__floats2half2_rn(b.z, b.w)));
}

// ============================================================================
// QKV projection, fp16 in/out: dst = fp16((X @ W^T + b) * s), s=1/8 for q.
// CTA 128x128, KC=32, 4-stage cp.async ring, ONE barrier per chunk.
// 8 warps = 4(M) x 2(N); warp tile 32x64.
// ============================================================================
#define KCH 32
#define QST 4
#define QKV_SMEM (QST * 128 * 40 * 2 * 2)   // As + Bs, 81920 B

__global__ __launch_bounds__(256, 2) void qkv_gemm_f16(
    const float* __restrict__ bq, const float* __restrict__ bk,
    const float* __restrict__ bv)
{
    extern __shared__ __align__(16) char smraw[];
    __half (*As)[128][40] = (__half (*)[128][40])smraw;
    __half (*Bs)[128][40] = (__half (*)[128][40])(smraw + QST * 128 * 40 * 2);

    const int z = blockIdx.z;
    const float* bias = (z == 0) ? bq : (z == 1) ? bk : bv;
    __half* dst       = (z == 0) ? g_qh : (z == 1) ? g_kh : g_vh;
    const __half* Wp  = g_wh + (size_t)z * DM * DM;

    const int tid = threadIdx.x;
    const int wid = tid >> 5, lane = tid & 31;
    const int wm = wid & 3, wn = wid >> 2;
    const int m0 = blockIdx.y * 128, n0 = blockIdx.x * 128;

    const int lrow = tid >> 1;            // 0..127
    const int lck = (tid & 1) * 16;       // half-offset: 0 or 16
    const __half* Ag = g_xh + (size_t)(m0 + lrow) * DM + lck;
    const __half* Bg = Wp + (size_t)(n0 + lrow) * DM + lck;

    float acc[2][8][4];
    #pragma unroll
    for (int mt = 0; mt < 2; mt++)
        #pragma unroll
        for (int nt = 0; nt < 8; nt++)
            #pragma unroll
            for (int j = 0; j < 4; j++) acc[mt][nt][j] = 0.f;

    const int fr = lane >> 2, fc = (lane & 3) * 2;
    const int lrow16 = lane & 15;
    const int chalf = (lane & 16) >> 1;   // 0 or 8 halves

    const int NCH = DM / KCH;   // 32

    // prologue: stage chunks 0 and 1
    #pragma unroll
    for (int p = 0; p < 2; p++) {
        const __half* An = Ag + p * KCH;
        const __half* Bn = Bg + p * KCH;
        CP16(smem_u32(&As[p][lrow][lck]),     An);
        CP16(smem_u32(&As[p][lrow][lck + 8]), An + 8);
        CP16(smem_u32(&Bs[p][lrow][lck]),     Bn);
        CP16(smem_u32(&Bs[p][lrow][lck + 8]), Bn + 8);
        CP_COMMIT();
    }

    for (int c = 0; c < NCH; c++) {
        if (c + 2 < NCH) {
            const int st = (c + 2) & 3;
            const __half* An = Ag + (c + 2) * KCH;
            const __half* Bn = Bg + (c + 2) * KCH;
            CP16(smem_u32(&As[st][lrow][lck]),     An);
            CP16(smem_u32(&As[st][lrow][lck + 8]), An + 8);
            CP16(smem_u32(&Bs[st][lrow][lck]),     Bn);
            CP16(smem_u32(&Bs[st][lrow][lck + 8]), Bn + 8);
            CP_COMMIT();
            CP_WAIT2();
        } else if (c + 1 < NCH) {
            CP_WAIT1();
        } else {
            CP_WAIT0();
        }
        __syncthreads();   // single barrier: data visible + prev readers done
        const int b = c & 3;

        #pragma unroll
        for (int kk = 0; kk < KCH; kk += 16) {
            uint32_t a[2][4];
            #pragma unroll
            for (int mt = 0; mt < 2; mt++)
                ldsm_x4(a[mt][0], a[mt][1], a[mt][2], a[mt][3],
                        smem_u32(&As[b][wm * 32 + mt * 16 + lrow16][kk + chalf]));
            #pragma unroll
            for (int g = 0; g < 4; g++) {
                uint32_t r0, r1, r2, r3;
                ldsm_x4(r0, r1, r2, r3,
                        smem_u32(&Bs[b][wn * 64 + g * 16 + lrow16][kk + chalf]));
                mma16816h(acc[0][2 * g],     a[0], r0, r2);
                mma16816h(acc[1][2 * g],     a[1], r0, r2);
                mma16816h(acc[0][2 * g + 1], a[0], r1, r3);
                mma16816h(acc[1][2 * g + 1], a[1], r1, r3);
            }
        }
    }

    // ---- epilogue: +bias, (q: *0.125), fp16, into [B, H, S, 64] scratch ----
    const float s = (z == 0) ? 0.125f : 1.0f;
    #pragma unroll
    for (int mt = 0; mt < 2; mt++) {
        const int row0 = m0 + wm * 32 + mt * 16 + fr;
        const int b0r = row0 >> 11, s0 = row0 & (SQ - 1);
        const int row1 = row0 + 8;
        const int b1r = row1 >> 11, s1 = row1 & (SQ - 1);
        #pragma unroll
        for (int nt = 0; nt < 8; nt++) {
            const int col = n0 + wn * 64 + nt * 8 + fc;
            const int h = col >> 6, dd = col & 63;
            const float bz0 = bias[col], bz1 = bias[col + 1];
            __half* p0 = dst + ((size_t)(b0r * NH + h) * SQ + s0) * HD + dd;
            __half* p1 = dst + ((size_t)(b1r * NH + h) * SQ + s1) * HD + dd;
            *(__half2*)p0 = __floats2half2_rn((acc[mt][nt][0] + bz0) * s,
                                              (acc[mt][nt][1] + bz1) * s);
            *(__half2*)p1 = __floats2half2_rn((acc[mt][nt][2] + bz0) * s,
                                              (acc[mt][nt][3] + bz1) * s);
        }
    }
}

// ============================================================================
// Flash attention: fp16 scratch in, 4-stage cp.async ring, ONE barrier per
// KV tile. CTA = 128 q-rows; 8 warps, each an m16 band; BK=64.
// ============================================================================
#define BQ 128
#define BK 64
#define VP 72
#define FST 4
#define FA_SMEM (FST * 2 * BK * VP * 2)   // 73728 B

__global__ __launch_bounds__(256, 2) void flash_attn_mma(
    const float* __restrict__ mask, float* __restrict__ out)
{
    extern __shared__ __align__(16) char smraw[];
    __half (*KVs)[2][BK][VP] = (__half (*)[2][BK][VP])smraw;

    const int tid = threadIdx.x;
    const int wid = tid >> 5, lane = tid & 31;
    const int fr = lane >> 2, fc = (lane & 3) * 2;
    const int bh = blockIdx.y;
    const int b = bh >> 4, h = bh & 15;
    const int q0 = blockIdx.x * BQ;
    const int qrow = q0 + wid * 16;

    const __half* Qg = g_qh + (size_t)bh * SQ * HD;
    const __half* Kg = g_kh + (size_t)bh * SQ * HD;
    const __half* Vg = g_vh + (size_t)bh * SQ * HD;
    const float* mrow = mask + (size_t)b * SQ;

    // ---- Q fragments: raw 32-bit loads from fp16 scratch (already scaled) ----
    uint32_t qf[4][4];
    #pragma unroll
    for (int kc = 0; kc < 4; kc++) {
        #pragma unroll
        for (int rr = 0; rr < 2; rr++) {
            const __half* p = Qg + (size_t)(qrow + fr + rr * 8) * HD + kc * 16 + fc;
            qf[kc][rr]     = *(const uint32_t*)p;
            qf[kc][rr + 2] = *(const uint32_t*)(p + 8);
        }
    }

    float accO[8][4];
    #pragma unroll
    for (int j = 0; j < 8; j++)
        #pragma unroll
        for (int i = 0; i < 4; i++) accO[j][i] = 0.f;
    float m0r = -1e30f, m1r = -1e30f, l0 = 0.f, l1 = 0.f;

    // cp.async mapping: 64 rows x 64 halves; 4 threads/row x 2 x 8 halves
    const int krow = tid >> 2;
    const int kcol = (tid & 3) * 16;      // halves

    const int NIT = SQ / BK;   // 32

    // prologue: stage tiles 0 and 1
    #pragma unroll
    for (int p = 0; p < 2; p++) {
        const __half* kp = Kg + (size_t)(p * BK + krow) * HD + kcol;
        const __half* vp = Vg + (size_t)(p * BK + krow) * HD + kcol;
        CP16(smem_u32(&KVs[p][0][krow][kcol]),     kp);
        CP16(smem_u32(&KVs[p][0][krow][kcol + 8]), kp + 8);
        CP16(smem_u32(&KVs[p][1][krow][kcol]),     vp);
        CP16(smem_u32(&KVs[p][1][krow][kcol + 8]), vp + 8);
        CP_COMMIT();
    }

    const int lrow16 = lane & 15;
    const int chalf = (lane & 16) >> 1;

    for (int it = 0; it < NIT; it++) {
        if (it + 2 < NIT) {
            const int st = (it + 2) & 3;
            const __half* kp = Kg + (size_t)((it + 2) * BK + krow) * HD + kcol;
            const __half* vp = Vg + (size_t)((it + 2) * BK + krow) * HD + kcol;
            CP16(smem_u32(&KVs[st][0][krow][kcol]),     kp);
            CP16(smem_u32(&KVs[st][0][krow][kcol + 8]), kp + 8);
            CP16(smem_u32(&KVs[st][1][krow][kcol]),     vp);
            CP16(smem_u32(&KVs[st][1][krow][kcol + 8]), vp + 8);
            CP_COMMIT();
            CP_WAIT2();
        } else if (it + 1 < NIT) {
            CP_WAIT1();
        } else {
            CP_WAIT0();
        }
        __syncthreads();   // single barrier per tile
        const int bf = it & 3;
        const uint32_t kh_b = smem_u32(&KVs[bf][0][0][0]);
        const uint32_t vh_b = smem_u32(&KVs[bf][1][0][0]);
        const int j0 = it * BK;

        // ---- prefetch mask values (LDG hidden under the MMAs below) ----
        float2 mv[8];
        #pragma unroll
        for (int j = 0; j < 8; j++)
            mv[j] = *(const float2*)(mrow + j0 + j * 8 + fc);

        // ---- S = Q K^T ----
        float sacc[8][4];
        #pragma unroll
        for (int j = 0; j < 8; j++)
            #pragma unroll
            for (int i = 0; i < 4; i++) sacc[j][i] = 0.f;

        #pragma unroll
        for (int kc = 0; kc < 4; kc++) {
            #pragma unroll
            for (int g = 0; g < 4; g++) {
                uint32_t r0, r1, r2, r3;
                uint32_t addr = kh_b +
                    ((g * 16 + lrow16) * VP + kc * 16 + chalf) * 2;
                ldsm_x4(r0, r1, r2, r3, addr);
                mma16816h(sacc[2 * g],     qf[kc], r0, r2);
                mma16816h(sacc[2 * g + 1], qf[kc], r1, r3);
            }
        }

        // ---- mask + online softmax ----
        #pragma unroll
        for (int j = 0; j < 8; j++) {
            sacc[j][0] += mv[j].x; sacc[j][1] += mv[j].y;
            sacc[j][2] += mv[j].x; sacc[j][3] += mv[j].y;
        }
        float rmax0 = -1e30f, rmax1 = -1e30f;
        #pragma unroll
        for (int j = 0; j < 8; j++) {
            rmax0 = fmaxf(rmax0, fmaxf(sacc[j][0], sacc[j][1]));
            rmax1 = fmaxf(rmax1, fmaxf(sacc[j][2], sacc[j][3]));
        }
        rmax0 = fmaxf(rmax0, __shfl_xor_sync(0xffffffffu, rmax0, 1));
        rmax0 = fmaxf(rmax0, __shfl_xor_sync(0xffffffffu, rmax0, 2));
        rmax1 = fmaxf(rmax1, __shfl_xor_sync(0xffffffffu, rmax1, 1));
        rmax1 = fmaxf(rmax1, __shfl_xor_sync(0xffffffffu, rmax1, 2));

        const float mn0 = fmaxf(m0r, rmax0);
        const float mn1 = fmaxf(m1r, rmax1);
        const float a0 = __expf(m0r - mn0);
        const float a1 = __expf(m1r - mn1);
        m0r = mn0; m1r = mn1;

        float ps0 = 0.f, ps1 = 0.f;
        uint32_t ph[16];
        #pragma unroll
        for (int j = 0; j < 8; j++) {
            float p0 = __expf(sacc[j][0] - mn0);
            float p1 = __expf(sacc[j][1] - mn0);
            float p2 = __expf(sacc[j][2] - mn1);
            float p3 = __expf(sacc[j][3] - mn1);
            ps0 += p0 + p1;
            ps1 += p2 + p3;
            ph[2 * j]     = h2bits(__floats2half2_rn(p0, p1));
            ph[2 * j + 1] = h2bits(__floats2half2_rn(p2, p3));
        }
        l0 = l0 * a0 + ps0;
        l1 = l1 * a1 + ps1;
        #pragma unroll
        for (int j = 0; j < 8; j++) {
            accO[j][0] *= a0; accO[j][1] *= a0;
            accO[j][2] *= a1; accO[j][3] *= a1;
        }

        // ---- O += P V ----
        #pragma unroll
        for (int kc = 0; kc < 4; kc++) {
            uint32_t pah[4] = { ph[4*kc], ph[4*kc+1], ph[4*kc+2], ph[4*kc+3] };
            #pragma unroll
            for (int dg = 0; dg < 4; dg++) {
                uint32_t off = vh_b + ((kc * 16 + lrow16) * VP + dg * 16 + chalf) * 2;
                uint32_t h0, h1, h2, h3;
                ldsm_x4_t(h0, h1, h2, h3, off);
                mma16816h(accO[2 * dg],     pah, h0, h1);
                mma16816h(accO[2 * dg + 1], pah, h2, h3);
            }
        }
    }

    // ---- epilogue ----
    l0 += __shfl_xor_sync(0xffffffffu, l0, 1);
    l0 += __shfl_xor_sync(0xffffffffu, l0, 2);
    l1 += __shfl_xor_sync(0xffffffffu, l1, 1);
    l1 += __shfl_xor_sync(0xffffffffu, l1, 2);
    const float inv0 = 1.0f / l0, inv1 = 1.0f / l1;

    const int s0 = qrow + fr, s1 = s0 + 8;
    float* o0 = out + ((size_t)b * SQ + s0) * DM + h * HD;
    float* o1 = out + ((size_t)b * SQ + s1) * DM + h * HD;
    #pragma unroll
    for (int dt = 0; dt < 8; dt++) {
        const int d = dt * 8 + fc;
        *(float2*)(o0 + d) = make_float2(accO[dt][0] * inv0, accO[dt][1] * inv0);
        *(float2*)(o1 + d) = make_float2(accO[dt][2] * inv1, accO[dt][3] * inv1);
    }
}

extern "C" void kernel_launch(void* const* d_in, const int* in_sizes, int n_in,
                              void* d_out, int out_size)
{
    const float* X   = (const float*)d_in[0];
    const float* Mk  = (const float*)d_in[1];
    const float* Wq  = (const float*)d_in[2];
    const float* bq  = (const float*)d_in[3];
    const float* Wk  = (const float*)d_in[4];
    const float* bk  = (const float*)d_in[5];
    const float* Wv  = (const float*)d_in[6];
    const float* bv  = (const float*)d_in[7];
    float* out = (float*)d_out;

    cudaFuncSetAttribute(qkv_gemm_f16,
                         cudaFuncAttributeMaxDynamicSharedMemorySize, QKV_SMEM);
    cudaFuncSetAttribute(flash_attn_mma,
                         cudaFuncAttributeMaxDynamicSharedMemorySize, FA_SMEM);

    cvt_x<<<NB * SQ * DM / 2048, 256>>>(X, NB * SQ * DM);
    cvt_w<<<3 * DM * DM / 2048, 256>>>(Wq, Wk, Wv);
    qkv_gemm_f16<<<dim3(8, 64, 3), 256, QKV_SMEM>>>(bq, bk, bv);
    flash_attn_mma<<<dim3(SQ / BQ, NB * NH), 256, FA_SMEM>>>(Mk, out);
}